// round 7
// baseline (speedup 1.0000x reference)
#include <cuda_runtime.h>
#include <cuda_bf16.h>
#include <mma.h>
#include <cstdint>
#include <cstddef>
#include <math_constants.h>

using namespace nvcuda;

// Problem constants
static constexpr int B  = 4;
static constexpr int S  = 2048;
static constexpr int E  = 1024;
static constexpr int H  = 16;
static constexpr int DK = 64;
static constexpr int BH = B * H;      // 64
static constexpr int M_TOK = B * S;   // 8192

// ---------------- scratch (device globals; no cudaMalloc allowed) ----------------
__device__ __nv_bfloat16 g_xhi[(size_t)M_TOK * E], g_xlo[(size_t)M_TOK * E];
__device__ __nv_bfloat16 g_Wqt_hi[(size_t)3 * E * E], g_Wqt_lo[(size_t)3 * E * E];
__device__ __nv_bfloat16 g_Wot_hi[(size_t)E * E],     g_Wot_lo[(size_t)E * E];
__device__ __nv_bfloat16 g_Qhi [(size_t)BH * S * DK], g_Qlo [(size_t)BH * S * DK];
__device__ __nv_bfloat16 g_Khi [(size_t)BH * S * DK], g_Klo [(size_t)BH * S * DK];
__device__ __nv_bfloat16 g_Vthi[(size_t)BH * DK * S], g_Vtlo[(size_t)BH * DK * S];
__device__ __nv_bfloat16 g_valshi[(size_t)M_TOK * E], g_valslo[(size_t)M_TOK * E];
// softmax partials: per (bh, row, 128-col block)
__device__ float g_pm[(size_t)BH * S * 16], g_ps[(size_t)BH * S * 16];
__device__ float g_rm[(size_t)BH * S],      g_ri[(size_t)BH * S];

// ---------------- helpers ----------------
__device__ __forceinline__ uint32_t smem_to_u32(const void* p) {
    uint32_t a;
    asm("{ .reg .u64 t; cvta.to.shared.u64 t, %1; cvt.u32.u64 %0, t; }" : "=r"(a) : "l"(p));
    return a;
}
__device__ __forceinline__ void cp_async16(uint32_t dst, const void* src) {
    asm volatile("cp.async.cg.shared.global [%0], [%1], 16;" :: "r"(dst), "l"(src));
}
#define CP_COMMIT() asm volatile("cp.async.commit_group;" ::: "memory")
#define CP_WAIT(N)  asm volatile("cp.async.wait_group %0;" :: "n"(N) : "memory")

__device__ __forceinline__ void split2(float v, __nv_bfloat16& h, __nv_bfloat16& l) {
    h = __float2bfloat16(v);
    l = __float2bfloat16(v - __bfloat162float(h));
}
__device__ __forceinline__ void pack_split2(float a, float b, uint32_t& hi, uint32_t& lo) {
    __nv_bfloat16 ha, la, hb, lb;
    split2(a, ha, la); split2(b, hb, lb);
    __nv_bfloat162 Hp(ha, hb), Lp(la, lb);
    hi = *reinterpret_cast<uint32_t*>(&Hp);
    lo = *reinterpret_cast<uint32_t*>(&Lp);
}

// ---------------- epilogues for projection GEMMs (BM=128, BN=256, LDC=264) --------
struct EpiQKV {
    const float* bias;
    __device__ void run(int /*z*/, int m0, int n0, int tid, const float* Cs) const {
        #pragma unroll
        for (int it = 0; it < 32; it++) {
            int idx = it * 256 + tid;
            int r = idx >> 6;
            int c4 = (idx & 63) * 4;
            float4 v = *reinterpret_cast<const float4*>(Cs + r * 264 + c4);
            int c = n0 + c4;
            v.x += bias[c]; v.y += bias[c + 1]; v.z += bias[c + 2]; v.w += bias[c + 3];
            int h = c / 192, cc = c - h * 192;
            int t = cc >> 6, d0 = cc & 63;
            int gr = m0 + r;
            int b = gr >> 11, s = gr & 2047;
            int bh = b * H + h;
            if (t == 2) {
                float vv[4] = {v.x, v.y, v.z, v.w};
                #pragma unroll
                for (int i = 0; i < 4; i++) {
                    __nv_bfloat16 hi, lo;
                    split2(vv[i], hi, lo);
                    size_t off = ((size_t)bh * DK + d0 + i) * S + s;
                    g_Vthi[off] = hi;
                    g_Vtlo[off] = lo;
                }
            } else {
                __nv_bfloat16* Dh = (t == 0) ? g_Qhi : g_Khi;
                __nv_bfloat16* Dl = (t == 0) ? g_Qlo : g_Klo;
                uint32_t h0, l0, h1, l1;
                pack_split2(v.x, v.y, h0, l0);
                pack_split2(v.z, v.w, h1, l1);
                size_t off = ((size_t)bh * S + s) * DK + d0;
                *reinterpret_cast<uint2*>(Dh + off) = make_uint2(h0, h1);
                *reinterpret_cast<uint2*>(Dl + off) = make_uint2(l0, l1);
            }
        }
    }
};

struct EpiLogits {
    float* attn;
    __device__ void run(int z, int m0, int n0, int tid, const float* Cs) const {
        float* dst = attn + (size_t)z * S * S;
        const int lane = tid & 31;
        #pragma unroll
        for (int it = 0; it < 32; it++) {
            int idx = it * 256 + tid;
            int r = idx >> 6;                 // constant within a warp
            int c4 = (idx & 63) * 4;          // warp spans one 128-col block
            float4 v = *reinterpret_cast<const float4*>(Cs + r * 264 + c4);
            v.x *= 0.125f; v.y *= 0.125f; v.z *= 0.125f; v.w *= 0.125f;
            *reinterpret_cast<float4*>(dst + (size_t)(m0 + r) * S + n0 + c4) = v;
            float tm = fmaxf(fmaxf(v.x, v.y), fmaxf(v.z, v.w));
            #pragma unroll
            for (int o = 16; o > 0; o >>= 1) tm = fmaxf(tm, __shfl_xor_sync(0xFFFFFFFFu, tm, o));
            float ts = __expf(v.x - tm) + __expf(v.y - tm) + __expf(v.z - tm) + __expf(v.w - tm);
            #pragma unroll
            for (int o = 16; o > 0; o >>= 1) ts += __shfl_xor_sync(0xFFFFFFFFu, ts, o);
            if (lane == 0) {
                int nb = (n0 >> 7) + ((idx >> 5) & 1);
                size_t pi = ((size_t)z * S + m0 + r) * 16 + nb;
                g_pm[pi] = tm;
                g_ps[pi] = ts;
            }
        }
    }
};

struct EpiOut {
    const float* bias;
    float* out;
    __device__ void run(int /*z*/, int m0, int n0, int tid, const float* Cs) const {
        #pragma unroll
        for (int it = 0; it < 32; it++) {
            int idx = it * 256 + tid;
            int r = idx >> 6;
            int c4 = (idx & 63) * 4;
            float4 v = *reinterpret_cast<const float4*>(Cs + r * 264 + c4);
            int c = n0 + c4;
            v.x += bias[c]; v.y += bias[c + 1]; v.z += bias[c + 2]; v.w += bias[c + 3];
            *reinterpret_cast<float4*>(out + (size_t)(m0 + r) * E + c) = v;
        }
    }
};

// ---------------- cp.async pipelined split-bf16 WMMA GEMM -------------------------
// BM=128, BN=256, BK=32, 8 warps as 2x4 grid of 64x64 warp tiles, 3-stage pipeline.
// D[M,N] = A[M,K] * B[N,K]^T ; 3 passes: Ah*Bh + Ah*Bl + Al*Bh, fp32 accum.
template<class Epi>
__global__ void __launch_bounds__(256, 1)
gemm_async(const __nv_bfloat16* __restrict__ Ahi, const __nv_bfloat16* __restrict__ Alo,
           const __nv_bfloat16* __restrict__ Bhi, const __nv_bfloat16* __restrict__ Blo,
           int K, size_t sAz, size_t sBz, Epi epi)
{
    constexpr int BM = 128, BN = 256;
    constexpr int LD = 40;                          // BK=32 + 8 pad
    constexpr int STG_BYTES = (2 * BM + 2 * BN) * LD * 2;   // 61440
    constexpr int LDC = BN + 8;                     // 264

    extern __shared__ char smem[];
    const uint32_t sbase = smem_to_u32(smem);
    const int tid = threadIdx.x, wid = tid >> 5;
    const int z = blockIdx.z;
    const int m0 = blockIdx.y * BM, n0 = blockIdx.x * BN;
    const int wm0 = (wid & 1) * 64, wn0 = (wid >> 1) * 64;

    Ahi += (size_t)z * sAz; Alo += (size_t)z * sAz;
    Bhi += (size_t)z * sBz; Blo += (size_t)z * sBz;

    const int nchunks = K >> 5;

    auto stage = [&](int s, int ch) {
        const int k0 = ch << 5;
        const uint32_t sA = sbase + s * STG_BYTES;
        const uint32_t sB = sA + 2 * BM * LD * 2;
        for (int u = tid; u < BM * 4; u += 256) {
            int r = u >> 2, g = u & 3;
            size_t gi = (size_t)(m0 + r) * K + k0 + g * 8;
            uint32_t so = sA + (uint32_t)(r * LD + g * 8) * 2;
            cp_async16(so, Ahi + gi);
            cp_async16(so + BM * LD * 2, Alo + gi);
        }
        for (int u = tid; u < BN * 4; u += 256) {
            int r = u >> 2, g = u & 3;
            size_t gi = (size_t)(n0 + r) * K + k0 + g * 8;
            uint32_t so = sB + (uint32_t)(r * LD + g * 8) * 2;
            cp_async16(so, Bhi + gi);
            cp_async16(so + BN * LD * 2, Blo + gi);
        }
        CP_COMMIT();
    };

    wmma::fragment<wmma::accumulator, 16, 16, 16, float> acc[4][4];
    #pragma unroll
    for (int mi = 0; mi < 4; mi++)
        #pragma unroll
        for (int ni = 0; ni < 4; ni++) wmma::fill_fragment(acc[mi][ni], 0.0f);

    stage(0, 0);
    if (nchunks > 1) stage(1, 1);

    for (int ch = 0; ch < nchunks; ch++) {
        if (ch + 2 < nchunks) { stage((ch + 2) % 3, ch + 2); CP_WAIT(2); }
        else if (ch + 1 < nchunks) { CP_WAIT(1); }
        else { CP_WAIT(0); }
        __syncthreads();

        const __nv_bfloat16* As_hi =
            reinterpret_cast<const __nv_bfloat16*>(smem + (ch % 3) * STG_BYTES);
        const __nv_bfloat16* As_lo = As_hi + BM * LD;
        const __nv_bfloat16* Bs_hi = As_lo + BM * LD;
        const __nv_bfloat16* Bs_lo = Bs_hi + BN * LD;

        #pragma unroll
        for (int ks = 0; ks < 2; ks++) {
            wmma::fragment<wmma::matrix_a, 16, 16, 16, __nv_bfloat16, wmma::row_major> ah[4], al[4];
            #pragma unroll
            for (int mi = 0; mi < 4; mi++) {
                wmma::load_matrix_sync(ah[mi], As_hi + (wm0 + mi * 16) * LD + ks * 16, LD);
                wmma::load_matrix_sync(al[mi], As_lo + (wm0 + mi * 16) * LD + ks * 16, LD);
            }
            #pragma unroll
            for (int ni = 0; ni < 4; ni++) {
                wmma::fragment<wmma::matrix_b, 16, 16, 16, __nv_bfloat16, wmma::col_major> bh, bl;
                wmma::load_matrix_sync(bh, Bs_hi + (wn0 + ni * 16) * LD + ks * 16, LD);
                wmma::load_matrix_sync(bl, Bs_lo + (wn0 + ni * 16) * LD + ks * 16, LD);
                #pragma unroll
                for (int mi = 0; mi < 4; mi++) {
                    wmma::mma_sync(acc[mi][ni], ah[mi], bh, acc[mi][ni]);
                    wmma::mma_sync(acc[mi][ni], ah[mi], bl, acc[mi][ni]);
                    wmma::mma_sync(acc[mi][ni], al[mi], bh, acc[mi][ni]);
                }
            }
        }
        __syncthreads();
    }

    float* Cs = reinterpret_cast<float*>(smem);
    #pragma unroll
    for (int mi = 0; mi < 4; mi++)
        #pragma unroll
        for (int ni = 0; ni < 4; ni++)
            wmma::store_matrix_sync(Cs + (wm0 + mi * 16) * LDC + wn0 + ni * 16,
                                    acc[mi][ni], LDC, wmma::mem_row_major);
    __syncthreads();
    epi.run(z, m0, n0, tid, Cs);
}

// ---------------- combine per-block softmax partials into per-row (m, 1/sum) -----
__global__ void __launch_bounds__(256)
rowreduce(const float* __restrict__ pm, const float* __restrict__ ps,
          float* __restrict__ rm, float* __restrict__ ri)
{
    int w = (blockIdx.x * 256 + threadIdx.x) >> 5;   // one warp per row
    int lane = threadIdx.x & 31;
    float m = -CUDART_INF_F, s = 0.0f;
    if (lane < 16) {
        m = pm[(size_t)w * 16 + lane];
        s = ps[(size_t)w * 16 + lane];
    }
    float gm = m;
    #pragma unroll
    for (int o = 16; o > 0; o >>= 1) gm = fmaxf(gm, __shfl_xor_sync(0xFFFFFFFFu, gm, o));
    float c = (lane < 16) ? s * __expf(m - gm) : 0.0f;
    #pragma unroll
    for (int o = 16; o > 0; o >>= 1) c += __shfl_xor_sync(0xFFFFFFFFu, c, o);
    if (lane == 0) {
        rm[w] = gm;
        ri[w] = 1.0f / c;
    }
}

// ---------------- PV kernel: fused softmax + probs write-back + split-bf16 WMMA ----
__global__ void __launch_bounds__(256, 2)
gemm_pv(float* __restrict__ attn, const float* __restrict__ rm, const float* __restrict__ ri,
        const __nv_bfloat16* __restrict__ Vthi, const __nv_bfloat16* __restrict__ Vtlo)
{
    constexpr int BM = 128, LD = 80, LDC = 72;
    constexpr int MI = 2, NI = 2;
    constexpr int OFF_A = 0;                        // Ash+Asl: 2*128*80*2 = 40960
    constexpr int OFF_V = 40960;                    // 2 stages * 20480
    constexpr int V_STG = 20480;
    constexpr int V_LO  = 10240;                    // lo offset within a V stage

    extern __shared__ char smem[];
    const uint32_t sbase = smem_to_u32(smem);
    __nv_bfloat16* Ash = reinterpret_cast<__nv_bfloat16*>(smem + OFF_A);
    __nv_bfloat16* Asl = Ash + BM * LD;
    float* Cs = reinterpret_cast<float*>(smem + OFF_A);

    const int tid = threadIdx.x, wid = tid >> 5;
    const int z = blockIdx.z;
    const int m0 = blockIdx.y * BM;
    const int wm0 = (wid & 3) * 32, wn0 = (wid >> 2) * 32;

    float* A = attn + (size_t)z * S * S;
    const __nv_bfloat16* Bh = Vthi + (size_t)z * DK * S;
    const __nv_bfloat16* Bl = Vtlo + (size_t)z * DK * S;

    auto stage_v = [&](int s, int ch) {
        int k0 = ch << 6;
        for (int u = tid; u < 64 * 8; u += 256) {
            int r = u >> 3, g = u & 7;
            uint32_t so = sbase + OFF_V + s * V_STG + (uint32_t)(r * LD + g * 8) * 2;
            cp_async16(so, Bh + (size_t)r * S + k0 + g * 8);
            cp_async16(so + V_LO, Bl + (size_t)r * S + k0 + g * 8);
        }
        CP_COMMIT();
    };

    wmma::fragment<wmma::accumulator, 16, 16, 16, float> acc[MI][NI];
    #pragma unroll
    for (int mi = 0; mi < MI; mi++)
        #pragma unroll
        for (int ni = 0; ni < NI; ni++) wmma::fill_fragment(acc[mi][ni], 0.0f);

    stage_v(0, 0);
    for (int ch = 0; ch < S / 64; ch++) {
        const int k0 = ch << 6;
        if (ch + 1 < S / 64) stage_v((ch + 1) & 1, ch + 1);

        for (int u = tid; u < BM * 8; u += 256) {
            int r = u >> 3, g = u & 7;
            size_t rowoff = (size_t)z * S + m0 + r;
            float m = rm[rowoff], rv = ri[rowoff];
            float* src = A + (size_t)(m0 + r) * S + k0 + g * 8;
            float4 v0 = *reinterpret_cast<const float4*>(src);
            float4 v1 = *reinterpret_cast<const float4*>(src + 4);
            v0.x = __expf(v0.x - m) * rv; v0.y = __expf(v0.y - m) * rv;
            v0.z = __expf(v0.z - m) * rv; v0.w = __expf(v0.w - m) * rv;
            v1.x = __expf(v1.x - m) * rv; v1.y = __expf(v1.y - m) * rv;
            v1.z = __expf(v1.z - m) * rv; v1.w = __expf(v1.w - m) * rv;
            *reinterpret_cast<float4*>(src)     = v0;
            *reinterpret_cast<float4*>(src + 4) = v1;
            uint32_t h0, l0, h1, l1, h2, l2, h3, l3;
            pack_split2(v0.x, v0.y, h0, l0);
            pack_split2(v0.z, v0.w, h1, l1);
            pack_split2(v1.x, v1.y, h2, l2);
            pack_split2(v1.z, v1.w, h3, l3);
            *reinterpret_cast<uint4*>(Ash + r * LD + g * 8) = make_uint4(h0, h1, h2, h3);
            *reinterpret_cast<uint4*>(Asl + r * LD + g * 8) = make_uint4(l0, l1, l2, l3);
        }
        if (ch + 1 < S / 64) { CP_WAIT(1); }
        else                 { CP_WAIT(0); }
        __syncthreads();

        const __nv_bfloat16* Bsh =
            reinterpret_cast<const __nv_bfloat16*>(smem + OFF_V + (ch & 1) * V_STG);
        const __nv_bfloat16* Bsl = Bsh + 64 * LD;

        #pragma unroll
        for (int ks = 0; ks < 4; ks++) {
            wmma::fragment<wmma::matrix_a, 16, 16, 16, __nv_bfloat16, wmma::row_major> ah[MI], al[MI];
            wmma::fragment<wmma::matrix_b, 16, 16, 16, __nv_bfloat16, wmma::col_major> bh[NI], bl[NI];
            #pragma unroll
            for (int mi = 0; mi < MI; mi++) {
                wmma::load_matrix_sync(ah[mi], Ash + (wm0 + mi * 16) * LD + ks * 16, LD);
                wmma::load_matrix_sync(al[mi], Asl + (wm0 + mi * 16) * LD + ks * 16, LD);
            }
            #pragma unroll
            for (int ni = 0; ni < NI; ni++) {
                wmma::load_matrix_sync(bh[ni], Bsh + (wn0 + ni * 16) * LD + ks * 16, LD);
                wmma::load_matrix_sync(bl[ni], Bsl + (wn0 + ni * 16) * LD + ks * 16, LD);
            }
            #pragma unroll
            for (int mi = 0; mi < MI; mi++)
                #pragma unroll
                for (int ni = 0; ni < NI; ni++) {
                    wmma::mma_sync(acc[mi][ni], ah[mi], bh[ni], acc[mi][ni]);
                    wmma::mma_sync(acc[mi][ni], ah[mi], bl[ni], acc[mi][ni]);
                    wmma::mma_sync(acc[mi][ni], al[mi], bh[ni], acc[mi][ni]);
                }
        }
        __syncthreads();
    }

    #pragma unroll
    for (int mi = 0; mi < MI; mi++)
        #pragma unroll
        for (int ni = 0; ni < NI; ni++)
            wmma::store_matrix_sync(Cs + (wm0 + mi * 16) * LDC + wn0 + ni * 16,
                                    acc[mi][ni], LDC, wmma::mem_row_major);
    __syncthreads();

    int b = z >> 4, h = z & 15;
    #pragma unroll
    for (int it = 0; it < 8; it++) {
        int idx = it * 256 + tid;
        int r = idx >> 4;
        int c4 = (idx & 15) * 4;
        float4 v = *reinterpret_cast<const float4*>(Cs + r * LDC + c4);
        uint32_t h0, l0, h1, l1;
        pack_split2(v.x, v.y, h0, l0);
        pack_split2(v.z, v.w, h1, l1);
        size_t off = (size_t)(b * S + m0 + r) * E + h * DK + c4;
        *reinterpret_cast<uint2*>(g_valshi + off) = make_uint2(h0, h1);
        *reinterpret_cast<uint2*>(g_valslo + off) = make_uint2(l0, l1);
    }
}

// ---------------- pre-kernels ----------------
__global__ void __launch_bounds__(256)
split_kernel(const float* __restrict__ src, __nv_bfloat16* __restrict__ dh,
             __nv_bfloat16* __restrict__ dl, size_t n)
{
    size_t i = ((size_t)blockIdx.x * 256 + threadIdx.x) * 4;
    if (i >= n) return;
    float4 v = *reinterpret_cast<const float4*>(src + i);
    uint32_t h0, l0, h1, l1;
    pack_split2(v.x, v.y, h0, l0);
    pack_split2(v.z, v.w, h1, l1);
    *reinterpret_cast<uint2*>(dh + i) = make_uint2(h0, h1);
    *reinterpret_cast<uint2*>(dl + i) = make_uint2(l0, l1);
}

__global__ void __launch_bounds__(256)
transpose_split(const float* __restrict__ W, __nv_bfloat16* __restrict__ Th,
                __nv_bfloat16* __restrict__ Tl, int R, int C)
{
    __shared__ float t[32][33];
    int c0 = blockIdx.x * 32, r0 = blockIdx.y * 32;
    int tx = threadIdx.x & 31, ty = threadIdx.x >> 5;
    for (int j = ty; j < 32; j += 8)
        t[j][tx] = W[(size_t)(r0 + j) * C + c0 + tx];
    __syncthreads();
    for (int j = ty; j < 32; j += 8) {
        float v = t[tx][j];
        __nv_bfloat16 hh, ll;
        split2(v, hh, ll);
        size_t o = (size_t)(c0 + j) * R + r0 + tx;
        Th[o] = hh;
        Tl[o] = ll;
    }
}

// ---------------- launch ----------------
extern "C" void kernel_launch(void* const* d_in, const int* /*in_sizes*/, int /*n_in*/,
                              void* d_out, int /*out_size*/)
{
    const float* x    = (const float*)d_in[0];
    const float* Wqkv = (const float*)d_in[1];
    const float* bqkv = (const float*)d_in[2];
    const float* Wout = (const float*)d_in[3];
    const float* bout = (const float*)d_in[4];

    float* out  = (float*)d_out;
    float* attn = out + (size_t)M_TOK * E;

    __nv_bfloat16 *xhi, *xlo, *Wqh, *Wql, *Woh, *Wol;
    __nv_bfloat16 *Qhi, *Qlo, *Khi, *Klo, *Vthi, *Vtlo, *Vh, *Vl;
    float *pm, *ps, *rm, *ri;
    cudaGetSymbolAddress((void**)&xhi,  g_xhi);
    cudaGetSymbolAddress((void**)&xlo,  g_xlo);
    cudaGetSymbolAddress((void**)&Wqh,  g_Wqt_hi);
    cudaGetSymbolAddress((void**)&Wql,  g_Wqt_lo);
    cudaGetSymbolAddress((void**)&Woh,  g_Wot_hi);
    cudaGetSymbolAddress((void**)&Wol,  g_Wot_lo);
    cudaGetSymbolAddress((void**)&Qhi,  g_Qhi);
    cudaGetSymbolAddress((void**)&Qlo,  g_Qlo);
    cudaGetSymbolAddress((void**)&Khi,  g_Khi);
    cudaGetSymbolAddress((void**)&Klo,  g_Klo);
    cudaGetSymbolAddress((void**)&Vthi, g_Vthi);
    cudaGetSymbolAddress((void**)&Vtlo, g_Vtlo);
    cudaGetSymbolAddress((void**)&Vh,   g_valshi);
    cudaGetSymbolAddress((void**)&Vl,   g_valslo);
    cudaGetSymbolAddress((void**)&pm,   g_pm);
    cudaGetSymbolAddress((void**)&ps,   g_ps);
    cudaGetSymbolAddress((void**)&rm,   g_rm);
    cudaGetSymbolAddress((void**)&ri,   g_ri);

    // smem: 3 stages * 61440 = 184320 ; epilogue scratch 128*264*4 = 135168
    constexpr int SM_BIG = 184320;
    constexpr int SM_PV  = 81920;
    cudaFuncSetAttribute(gemm_async<EpiQKV>,
                         cudaFuncAttributeMaxDynamicSharedMemorySize, SM_BIG);
    cudaFuncSetAttribute(gemm_async<EpiLogits>,
                         cudaFuncAttributeMaxDynamicSharedMemorySize, SM_BIG);
    cudaFuncSetAttribute(gemm_async<EpiOut>,
                         cudaFuncAttributeMaxDynamicSharedMemorySize, SM_BIG);
    cudaFuncSetAttribute(gemm_pv,
                         cudaFuncAttributeMaxDynamicSharedMemorySize, SM_PV);

    // 0) operand prep
    transpose_split<<<dim3(3 * E / 32, E / 32), 256>>>(Wqkv, Wqh, Wql, E, 3 * E);
    transpose_split<<<dim3(E / 32, E / 32), 256>>>(Wout, Woh, Wol, E, E);
    split_kernel<<<(unsigned)((size_t)M_TOK * E / 4 / 256), 256>>>(x, xhi, xlo, (size_t)M_TOK * E);

    // 1) QKV projection -> split-scatter into Q/K/Vt
    gemm_async<EpiQKV><<<dim3(3 * E / 256, M_TOK / 128, 1), 256, SM_BIG>>>(
        xhi, xlo, Wqh, Wql, E, 0, 0, EpiQKV{bqkv});

    // 2) logits = Q*K^T/8 -> attn (raw), plus per-block softmax partials
    gemm_async<EpiLogits><<<dim3(S / 256, S / 128, BH), 256, SM_BIG>>>(
        Qhi, Qlo, Khi, Klo, DK, (size_t)S * DK, (size_t)S * DK, EpiLogits{attn});

    // 3) combine partials -> per-row (max, 1/sum)
    rowreduce<<<(unsigned)((size_t)BH * S * 32 / 256), 256>>>(pm, ps, rm, ri);

    // 4) PV: fused softmax (writes probs into attn) + values GEMM
    gemm_pv<<<dim3(1, S / 128, BH), 256, SM_PV>>>(attn, rm, ri, Vthi, Vtlo);

    // 5) output projection
    gemm_async<EpiOut><<<dim3(E / 256, M_TOK / 128, 1), 256, SM_BIG>>>(
        Vh, Vl, Woh, Wol, E, 0, 0, EpiOut{bout, out});
}

// round 8
// speedup vs baseline: 1.1235x; 1.1235x over previous
#include <cuda_runtime.h>
#include <cuda_bf16.h>
#include <mma.h>
#include <cstdint>
#include <cstddef>
#include <math_constants.h>

using namespace nvcuda;

// Problem constants
static constexpr int B  = 4;
static constexpr int S  = 2048;
static constexpr int E  = 1024;
static constexpr int H  = 16;
static constexpr int DK = 64;
static constexpr int BH = B * H;      // 64
static constexpr int M_TOK = B * S;   // 8192

// ---------------- scratch (device globals; no cudaMalloc allowed) ----------------
__device__ __nv_bfloat16 g_xhi[(size_t)M_TOK * E], g_xlo[(size_t)M_TOK * E];
__device__ __nv_bfloat16 g_Wqt_hi[(size_t)3 * E * E], g_Wqt_lo[(size_t)3 * E * E];
__device__ __nv_bfloat16 g_Wot_hi[(size_t)E * E],     g_Wot_lo[(size_t)E * E];
__device__ __nv_bfloat16 g_Qhi [(size_t)BH * S * DK], g_Qlo [(size_t)BH * S * DK];
__device__ __nv_bfloat16 g_Khi [(size_t)BH * S * DK], g_Klo [(size_t)BH * S * DK];
__device__ __nv_bfloat16 g_Vthi[(size_t)BH * DK * S], g_Vtlo[(size_t)BH * DK * S];
__device__ __nv_bfloat16 g_valshi[(size_t)M_TOK * E], g_valslo[(size_t)M_TOK * E];
// softmax partials: per (bh, row, 128-col block)
__device__ float g_pm[(size_t)BH * S * 16], g_ps[(size_t)BH * S * 16];
__device__ float g_rm[(size_t)BH * S],      g_ri[(size_t)BH * S];

// ---------------- helpers ----------------
__device__ __forceinline__ uint32_t smem_to_u32(const void* p) {
    uint32_t a;
    asm("{ .reg .u64 t; cvta.to.shared.u64 t, %1; cvt.u32.u64 %0, t; }" : "=r"(a) : "l"(p));
    return a;
}
__device__ __forceinline__ void cp_async16(uint32_t dst, const void* src) {
    asm volatile("cp.async.cg.shared.global [%0], [%1], 16;" :: "r"(dst), "l"(src));
}
#define CP_COMMIT() asm volatile("cp.async.commit_group;" ::: "memory")
#define CP_WAIT(N)  asm volatile("cp.async.wait_group %0;" :: "n"(N) : "memory")

__device__ __forceinline__ void split2(float v, __nv_bfloat16& h, __nv_bfloat16& l) {
    h = __float2bfloat16(v);
    l = __float2bfloat16(v - __bfloat162float(h));
}
__device__ __forceinline__ void pack_split2(float a, float b, uint32_t& hi, uint32_t& lo) {
    __nv_bfloat16 ha, la, hb, lb;
    split2(a, ha, la); split2(b, hb, lb);
    __nv_bfloat162 Hp(ha, hb), Lp(la, lb);
    hi = *reinterpret_cast<uint32_t*>(&Hp);
    lo = *reinterpret_cast<uint32_t*>(&Lp);
}

// ---------------- epilogues for projection GEMMs (BN=128, LDC=136) ----------------
struct EpiQKV {
    const float* bias;
    __device__ void run(int /*z*/, int m0, int n0, int tid, const float* Cs) const {
        #pragma unroll
        for (int it = 0; it < 16; it++) {
            int idx = it * 256 + tid;
            int r = idx >> 5;
            int c4 = (idx & 31) * 4;
            float4 v = *reinterpret_cast<const float4*>(Cs + r * 136 + c4);
            int c = n0 + c4;
            v.x += bias[c]; v.y += bias[c + 1]; v.z += bias[c + 2]; v.w += bias[c + 3];
            int h = c / 192, cc = c - h * 192;
            int t = cc >> 6, d0 = cc & 63;
            int gr = m0 + r;
            int b = gr >> 11, s = gr & 2047;
            int bh = b * H + h;
            if (t == 2) {
                float vv[4] = {v.x, v.y, v.z, v.w};
                #pragma unroll
                for (int i = 0; i < 4; i++) {
                    __nv_bfloat16 hi, lo;
                    split2(vv[i], hi, lo);
                    size_t off = ((size_t)bh * DK + d0 + i) * S + s;
                    g_Vthi[off] = hi;
                    g_Vtlo[off] = lo;
                }
            } else {
                __nv_bfloat16* Dh = (t == 0) ? g_Qhi : g_Khi;
                __nv_bfloat16* Dl = (t == 0) ? g_Qlo : g_Klo;
                uint32_t h0, l0, h1, l1;
                pack_split2(v.x, v.y, h0, l0);
                pack_split2(v.z, v.w, h1, l1);
                size_t off = ((size_t)bh * S + s) * DK + d0;
                *reinterpret_cast<uint2*>(Dh + off) = make_uint2(h0, h1);
                *reinterpret_cast<uint2*>(Dl + off) = make_uint2(l0, l1);
            }
        }
    }
};

struct EpiLogits {
    float* attn;
    __device__ void run(int z, int m0, int n0, int tid, const float* Cs) const {
        float* dst = attn + (size_t)z * S * S;
        const int lane = tid & 31;
        const int nb = n0 >> 7;
        #pragma unroll
        for (int it = 0; it < 16; it++) {
            int idx = it * 256 + tid;
            int r = idx >> 5;          // warp covers one full 128-col row segment
            int c4 = lane * 4;
            float4 v = *reinterpret_cast<const float4*>(Cs + r * 136 + c4);
            v.x *= 0.125f; v.y *= 0.125f; v.z *= 0.125f; v.w *= 0.125f;
            *reinterpret_cast<float4*>(dst + (size_t)(m0 + r) * S + n0 + c4) = v;
            float tm = fmaxf(fmaxf(v.x, v.y), fmaxf(v.z, v.w));
            #pragma unroll
            for (int o = 16; o > 0; o >>= 1) tm = fmaxf(tm, __shfl_xor_sync(0xFFFFFFFFu, tm, o));
            float ts = __expf(v.x - tm) + __expf(v.y - tm) + __expf(v.z - tm) + __expf(v.w - tm);
            #pragma unroll
            for (int o = 16; o > 0; o >>= 1) ts += __shfl_xor_sync(0xFFFFFFFFu, ts, o);
            if (lane == 0) {
                size_t pi = ((size_t)z * S + m0 + r) * 16 + nb;
                g_pm[pi] = tm;
                g_ps[pi] = ts;
            }
        }
    }
};

struct EpiOut {
    const float* bias;
    float* out;
    __device__ void run(int /*z*/, int m0, int n0, int tid, const float* Cs) const {
        #pragma unroll
        for (int it = 0; it < 16; it++) {
            int idx = it * 256 + tid;
            int r = idx >> 5;
            int c4 = (idx & 31) * 4;
            float4 v = *reinterpret_cast<const float4*>(Cs + r * 136 + c4);
            int c = n0 + c4;
            v.x += bias[c]; v.y += bias[c + 1]; v.z += bias[c + 2]; v.w += bias[c + 3];
            *reinterpret_cast<float4*>(out + (size_t)(m0 + r) * E + c) = v;
        }
    }
};

// ---------------- cp.async pipelined split-bf16 WMMA GEMM (BK=32, 2 CTAs/SM) ------
// D[M,N] = A[M,K] * B[N,K]^T ; A,B K-major bf16 hi/lo. 3 passes into fp32 accum.
template<int BM, int BN, class Epi>
__global__ void __launch_bounds__(256, 2)
gemm_async(const __nv_bfloat16* __restrict__ Ahi, const __nv_bfloat16* __restrict__ Alo,
           const __nv_bfloat16* __restrict__ Bhi, const __nv_bfloat16* __restrict__ Blo,
           int K, size_t sAz, size_t sBz, Epi epi)
{
    constexpr int LD = 40;                          // BK=32 + 8 pad
    constexpr int STG_BYTES = (2 * BM + 2 * BN) * LD * 2;
    constexpr int WM = 32, WN = BN / 2;
    constexpr int MI = WM / 16, NI = WN / 16;
    constexpr int LDC = BN + 8;

    extern __shared__ char smem[];
    const uint32_t sbase = smem_to_u32(smem);
    const int tid = threadIdx.x, wid = tid >> 5;
    const int z = blockIdx.z;
    const int m0 = blockIdx.y * BM, n0 = blockIdx.x * BN;
    const int wm0 = (wid & 3) * WM, wn0 = (wid >> 2) * WN;

    Ahi += (size_t)z * sAz; Alo += (size_t)z * sAz;
    Bhi += (size_t)z * sBz; Blo += (size_t)z * sBz;

    const int nchunks = K >> 5;

    auto stage = [&](int s, int ch) {
        const int k0 = ch << 5;
        const uint32_t sA = sbase + s * STG_BYTES;
        const uint32_t sB = sA + 2 * BM * LD * 2;
        for (int u = tid; u < BM * 4; u += 256) {
            int r = u >> 2, g = u & 3;
            size_t gi = (size_t)(m0 + r) * K + k0 + g * 8;
            uint32_t so = sA + (uint32_t)(r * LD + g * 8) * 2;
            cp_async16(so, Ahi + gi);
            cp_async16(so + BM * LD * 2, Alo + gi);
        }
        for (int u = tid; u < BN * 4; u += 256) {
            int r = u >> 2, g = u & 3;
            size_t gi = (size_t)(n0 + r) * K + k0 + g * 8;
            uint32_t so = sB + (uint32_t)(r * LD + g * 8) * 2;
            cp_async16(so, Bhi + gi);
            cp_async16(so + BN * LD * 2, Blo + gi);
        }
        CP_COMMIT();
    };

    wmma::fragment<wmma::accumulator, 16, 16, 16, float> acc[MI][NI];
    #pragma unroll
    for (int mi = 0; mi < MI; mi++)
        #pragma unroll
        for (int ni = 0; ni < NI; ni++) wmma::fill_fragment(acc[mi][ni], 0.0f);

    stage(0, 0);
    for (int ch = 0; ch < nchunks; ch++) {
        if (ch + 1 < nchunks) { stage((ch + 1) & 1, ch + 1); CP_WAIT(1); }
        else                  { CP_WAIT(0); }
        __syncthreads();

        const __nv_bfloat16* As_hi =
            reinterpret_cast<const __nv_bfloat16*>(smem + (ch & 1) * STG_BYTES);
        const __nv_bfloat16* As_lo = As_hi + BM * LD;
        const __nv_bfloat16* Bs_hi = As_lo + BM * LD;
        const __nv_bfloat16* Bs_lo = Bs_hi + BN * LD;

        #pragma unroll
        for (int ks = 0; ks < 2; ks++) {
            wmma::fragment<wmma::matrix_a, 16, 16, 16, __nv_bfloat16, wmma::row_major> ah[MI], al[MI];
            wmma::fragment<wmma::matrix_b, 16, 16, 16, __nv_bfloat16, wmma::col_major> bh[NI], bl[NI];
            #pragma unroll
            for (int mi = 0; mi < MI; mi++) {
                wmma::load_matrix_sync(ah[mi], As_hi + (wm0 + mi * 16) * LD + ks * 16, LD);
                wmma::load_matrix_sync(al[mi], As_lo + (wm0 + mi * 16) * LD + ks * 16, LD);
            }
            #pragma unroll
            for (int ni = 0; ni < NI; ni++) {
                wmma::load_matrix_sync(bh[ni], Bs_hi + (wn0 + ni * 16) * LD + ks * 16, LD);
                wmma::load_matrix_sync(bl[ni], Bs_lo + (wn0 + ni * 16) * LD + ks * 16, LD);
            }
            #pragma unroll
            for (int mi = 0; mi < MI; mi++)
                #pragma unroll
                for (int ni = 0; ni < NI; ni++) {
                    wmma::mma_sync(acc[mi][ni], ah[mi], bh[ni], acc[mi][ni]);
                    wmma::mma_sync(acc[mi][ni], ah[mi], bl[ni], acc[mi][ni]);
                    wmma::mma_sync(acc[mi][ni], al[mi], bh[ni], acc[mi][ni]);
                }
        }
        __syncthreads();
    }

    float* Cs = reinterpret_cast<float*>(smem);
    #pragma unroll
    for (int mi = 0; mi < MI; mi++)
        #pragma unroll
        for (int ni = 0; ni < NI; ni++)
            wmma::store_matrix_sync(Cs + (wm0 + mi * 16) * LDC + wn0 + ni * 16,
                                    acc[mi][ni], LDC, wmma::mem_row_major);
    __syncthreads();
    epi.run(z, m0, n0, tid, Cs);
}

// ---------------- combine per-block softmax partials into per-row (m, 1/sum) -----
__global__ void __launch_bounds__(256)
rowreduce(const float* __restrict__ pm, const float* __restrict__ ps,
          float* __restrict__ rm, float* __restrict__ ri)
{
    int w = (blockIdx.x * 256 + threadIdx.x) >> 5;   // one warp per row
    int lane = threadIdx.x & 31;
    float m = -CUDART_INF_F, s = 0.0f;
    if (lane < 16) {
        m = pm[(size_t)w * 16 + lane];
        s = ps[(size_t)w * 16 + lane];
    }
    float gm = m;
    #pragma unroll
    for (int o = 16; o > 0; o >>= 1) gm = fmaxf(gm, __shfl_xor_sync(0xFFFFFFFFu, gm, o));
    float c = (lane < 16) ? s * __expf(m - gm) : 0.0f;
    #pragma unroll
    for (int o = 16; o > 0; o >>= 1) c += __shfl_xor_sync(0xFFFFFFFFu, c, o);
    if (lane == 0) {
        rm[w] = gm;
        ri[w] = 1.0f / c;
    }
}

// ---------------- PV kernel: softmax+probs+PV, FULLY double-buffered --------------
// values[z](128 rows, 64 cols) = softmax(logits) @ V ; writes probs into attn.
// Both V (cp.async) and the A-transform are pipelined one chunk ahead so the
// transform's global loads/exp overlap the previous chunk's MMAs.
__global__ void __launch_bounds__(256, 2)
gemm_pv(float* __restrict__ attn, const float* __restrict__ rm, const float* __restrict__ ri,
        const __nv_bfloat16* __restrict__ Vthi, const __nv_bfloat16* __restrict__ Vtlo)
{
    constexpr int BM = 128, LDA = 72, LDV = 80, LDC = 72;
    constexpr int MI = 2, NI = 2;
    constexpr int A_STG = 2 * BM * LDA * 2;        // hi+lo per buffer = 36864
    constexpr int OFF_A = 0;                       // 2 buffers: 73728
    constexpr int OFF_V = 73728;                   // 2 stages * 20480 = 40960
    constexpr int V_STG = 20480;
    constexpr int V_LO  = 10240;
    constexpr int NC = S / 64;                     // 32 chunks

    extern __shared__ char smem[];
    const uint32_t sbase = smem_to_u32(smem);
    const int tid = threadIdx.x, wid = tid >> 5;
    const int z = blockIdx.z;
    const int m0 = blockIdx.y * BM;
    const int wm0 = (wid & 3) * 32, wn0 = (wid >> 2) * 32;

    float* A = attn + (size_t)z * S * S;
    const __nv_bfloat16* Bh = Vthi + (size_t)z * DK * S;
    const __nv_bfloat16* Bl = Vtlo + (size_t)z * DK * S;

    auto stage_v = [&](int s, int ch) {
        int k0 = ch << 6;
        for (int u = tid; u < 64 * 8; u += 256) {
            int r = u >> 3, g = u & 7;
            uint32_t so = sbase + OFF_V + s * V_STG + (uint32_t)(r * LDV + g * 8) * 2;
            cp_async16(so, Bh + (size_t)r * S + k0 + g * 8);
            cp_async16(so + V_LO, Bl + (size_t)r * S + k0 + g * 8);
        }
        CP_COMMIT();
    };

    // A transform: raw logits -> probs (write back) -> bf16 hi/lo into buffer s
    auto transform = [&](int s, int ch) {
        const int k0 = ch << 6;
        __nv_bfloat16* Ash = reinterpret_cast<__nv_bfloat16*>(smem + OFF_A + s * A_STG);
        __nv_bfloat16* Asl = Ash + BM * LDA;
        for (int u = tid; u < BM * 8; u += 256) {
            int r = u >> 3, g = u & 7;
            size_t rowoff = (size_t)z * S + m0 + r;
            float m = rm[rowoff], rv = ri[rowoff];
            float* src = A + (size_t)(m0 + r) * S + k0 + g * 8;
            float4 v0 = *reinterpret_cast<const float4*>(src);
            float4 v1 = *reinterpret_cast<const float4*>(src + 4);
            v0.x = __expf(v0.x - m) * rv; v0.y = __expf(v0.y - m) * rv;
            v0.z = __expf(v0.z - m) * rv; v0.w = __expf(v0.w - m) * rv;
            v1.x = __expf(v1.x - m) * rv; v1.y = __expf(v1.y - m) * rv;
            v1.z = __expf(v1.z - m) * rv; v1.w = __expf(v1.w - m) * rv;
            *reinterpret_cast<float4*>(src)     = v0;
            *reinterpret_cast<float4*>(src + 4) = v1;
            uint32_t h0, l0, h1, l1, h2, l2, h3, l3;
            pack_split2(v0.x, v0.y, h0, l0);
            pack_split2(v0.z, v0.w, h1, l1);
            pack_split2(v1.x, v1.y, h2, l2);
            pack_split2(v1.z, v1.w, h3, l3);
            *reinterpret_cast<uint4*>(Ash + r * LDA + g * 8) = make_uint4(h0, h1, h2, h3);
            *reinterpret_cast<uint4*>(Asl + r * LDA + g * 8) = make_uint4(l0, l1, l2, l3);
        }
    };

    wmma::fragment<wmma::accumulator, 16, 16, 16, float> acc[MI][NI];
    #pragma unroll
    for (int mi = 0; mi < MI; mi++)
        #pragma unroll
        for (int ni = 0; ni < NI; ni++) wmma::fill_fragment(acc[mi][ni], 0.0f);

    // prologue
    stage_v(0, 0);
    transform(0, 0);

    for (int ch = 0; ch < NC; ch++) {
        __syncthreads();   // A buf (ch&1) + previous-V consumption boundary

        // prefetch next chunk: V via cp.async, A transform into alternate buffer.
        // These global loads overlap the MMAs below.
        if (ch + 1 < NC) {
            stage_v((ch + 1) & 1, ch + 1);
            transform((ch + 1) & 1, ch + 1);
            CP_WAIT(1);    // V(ch) complete; V(ch+1) still in flight
        } else {
            CP_WAIT(0);
        }

        const __nv_bfloat16* Ash =
            reinterpret_cast<const __nv_bfloat16*>(smem + OFF_A + (ch & 1) * A_STG);
        const __nv_bfloat16* Asl = Ash + BM * LDA;
        const __nv_bfloat16* Bsh =
            reinterpret_cast<const __nv_bfloat16*>(smem + OFF_V + (ch & 1) * V_STG);
        const __nv_bfloat16* Bsl = Bsh + 64 * LDV;

        #pragma unroll
        for (int ks = 0; ks < 4; ks++) {
            wmma::fragment<wmma::matrix_a, 16, 16, 16, __nv_bfloat16, wmma::row_major> ah[MI], al[MI];
            wmma::fragment<wmma::matrix_b, 16, 16, 16, __nv_bfloat16, wmma::col_major> bh[NI], bl[NI];
            #pragma unroll
            for (int mi = 0; mi < MI; mi++) {
                wmma::load_matrix_sync(ah[mi], Ash + (wm0 + mi * 16) * LDA + ks * 16, LDA);
                wmma::load_matrix_sync(al[mi], Asl + (wm0 + mi * 16) * LDA + ks * 16, LDA);
            }
            #pragma unroll
            for (int ni = 0; ni < NI; ni++) {
                wmma::load_matrix_sync(bh[ni], Bsh + (wn0 + ni * 16) * LDV + ks * 16, LDV);
                wmma::load_matrix_sync(bl[ni], Bsl + (wn0 + ni * 16) * LDV + ks * 16, LDV);
            }
            #pragma unroll
            for (int mi = 0; mi < MI; mi++)
                #pragma unroll
                for (int ni = 0; ni < NI; ni++) {
                    wmma::mma_sync(acc[mi][ni], ah[mi], bh[ni], acc[mi][ni]);
                    wmma::mma_sync(acc[mi][ni], ah[mi], bl[ni], acc[mi][ni]);
                    wmma::mma_sync(acc[mi][ni], al[mi], bh[ni], acc[mi][ni]);
                }
        }
    }
    __syncthreads();

    float* Cs = reinterpret_cast<float*>(smem);
    #pragma unroll
    for (int mi = 0; mi < MI; mi++)
        #pragma unroll
        for (int ni = 0; ni < NI; ni++)
            wmma::store_matrix_sync(Cs + (wm0 + mi * 16) * LDC + wn0 + ni * 16,
                                    acc[mi][ni], LDC, wmma::mem_row_major);
    __syncthreads();

    int b = z >> 4, h = z & 15;
    #pragma unroll
    for (int it = 0; it < 8; it++) {
        int idx = it * 256 + tid;
        int r = idx >> 4;
        int c4 = (idx & 15) * 4;
        float4 v = *reinterpret_cast<const float4*>(Cs + r * LDC + c4);
        uint32_t h0, l0, h1, l1;
        pack_split2(v.x, v.y, h0, l0);
        pack_split2(v.z, v.w, h1, l1);
        size_t off = (size_t)(b * S + m0 + r) * E + h * DK + c4;
        *reinterpret_cast<uint2*>(g_valshi + off) = make_uint2(h0, h1);
        *reinterpret_cast<uint2*>(g_valslo + off) = make_uint2(l0, l1);
    }
}

// ---------------- pre-kernels ----------------
__global__ void __launch_bounds__(256)
split_kernel(const float* __restrict__ src, __nv_bfloat16* __restrict__ dh,
             __nv_bfloat16* __restrict__ dl, size_t n)
{
    size_t i = ((size_t)blockIdx.x * 256 + threadIdx.x) * 4;
    if (i >= n) return;
    float4 v = *reinterpret_cast<const float4*>(src + i);
    uint32_t h0, l0, h1, l1;
    pack_split2(v.x, v.y, h0, l0);
    pack_split2(v.z, v.w, h1, l1);
    *reinterpret_cast<uint2*>(dh + i) = make_uint2(h0, h1);
    *reinterpret_cast<uint2*>(dl + i) = make_uint2(l0, l1);
}

__global__ void __launch_bounds__(256)
transpose_split(const float* __restrict__ W, __nv_bfloat16* __restrict__ Th,
                __nv_bfloat16* __restrict__ Tl, int R, int C)
{
    __shared__ float t[32][33];
    int c0 = blockIdx.x * 32, r0 = blockIdx.y * 32;
    int tx = threadIdx.x & 31, ty = threadIdx.x >> 5;
    for (int j = ty; j < 32; j += 8)
        t[j][tx] = W[(size_t)(r0 + j) * C + c0 + tx];
    __syncthreads();
    for (int j = ty; j < 32; j += 8) {
        float v = t[tx][j];
        __nv_bfloat16 hh, ll;
        split2(v, hh, ll);
        size_t o = (size_t)(c0 + j) * R + r0 + tx;
        Th[o] = hh;
        Tl[o] = ll;
    }
}

// ---------------- launch ----------------
extern "C" void kernel_launch(void* const* d_in, const int* /*in_sizes*/, int /*n_in*/,
                              void* d_out, int /*out_size*/)
{
    const float* x    = (const float*)d_in[0];
    const float* Wqkv = (const float*)d_in[1];
    const float* bqkv = (const float*)d_in[2];
    const float* Wout = (const float*)d_in[3];
    const float* bout = (const float*)d_in[4];

    float* out  = (float*)d_out;
    float* attn = out + (size_t)M_TOK * E;

    __nv_bfloat16 *xhi, *xlo, *Wqh, *Wql, *Woh, *Wol;
    __nv_bfloat16 *Qhi, *Qlo, *Khi, *Klo, *Vthi, *Vtlo, *Vh, *Vl;
    float *pm, *ps, *rm, *ri;
    cudaGetSymbolAddress((void**)&xhi,  g_xhi);
    cudaGetSymbolAddress((void**)&xlo,  g_xlo);
    cudaGetSymbolAddress((void**)&Wqh,  g_Wqt_hi);
    cudaGetSymbolAddress((void**)&Wql,  g_Wqt_lo);
    cudaGetSymbolAddress((void**)&Woh,  g_Wot_hi);
    cudaGetSymbolAddress((void**)&Wol,  g_Wot_lo);
    cudaGetSymbolAddress((void**)&Qhi,  g_Qhi);
    cudaGetSymbolAddress((void**)&Qlo,  g_Qlo);
    cudaGetSymbolAddress((void**)&Khi,  g_Khi);
    cudaGetSymbolAddress((void**)&Klo,  g_Klo);
    cudaGetSymbolAddress((void**)&Vthi, g_Vthi);
    cudaGetSymbolAddress((void**)&Vtlo, g_Vtlo);
    cudaGetSymbolAddress((void**)&Vh,   g_valshi);
    cudaGetSymbolAddress((void**)&Vl,   g_valslo);
    cudaGetSymbolAddress((void**)&pm,   g_pm);
    cudaGetSymbolAddress((void**)&ps,   g_ps);
    cudaGetSymbolAddress((void**)&rm,   g_rm);
    cudaGetSymbolAddress((void**)&ri,   g_ri);

    constexpr int SM_BIG = 2 * (2 * 128 + 2 * 128) * 40 * 2;   // 81920 (2 stages, BK=32)
    constexpr int SM_PV  = 73728 + 40960;                      // 114688
    cudaFuncSetAttribute(gemm_async<128, 128, EpiQKV>,
                         cudaFuncAttributeMaxDynamicSharedMemorySize, SM_BIG);
    cudaFuncSetAttribute(gemm_async<128, 128, EpiLogits>,
                         cudaFuncAttributeMaxDynamicSharedMemorySize, SM_BIG);
    cudaFuncSetAttribute(gemm_async<128, 128, EpiOut>,
                         cudaFuncAttributeMaxDynamicSharedMemorySize, SM_BIG);
    cudaFuncSetAttribute(gemm_pv,
                         cudaFuncAttributeMaxDynamicSharedMemorySize, SM_PV);

    // 0) operand prep
    transpose_split<<<dim3(3 * E / 32, E / 32), 256>>>(Wqkv, Wqh, Wql, E, 3 * E);
    transpose_split<<<dim3(E / 32, E / 32), 256>>>(Wout, Woh, Wol, E, E);
    split_kernel<<<(unsigned)((size_t)M_TOK * E / 4 / 256), 256>>>(x, xhi, xlo, (size_t)M_TOK * E);

    // 1) QKV projection -> split-scatter into Q/K/Vt
    gemm_async<128, 128, EpiQKV><<<dim3(3 * E / 128, M_TOK / 128, 1), 256, SM_BIG>>>(
        xhi, xlo, Wqh, Wql, E, 0, 0, EpiQKV{bqkv});

    // 2) logits = Q*K^T/8 -> attn (raw), plus per-block softmax partials
    gemm_async<128, 128, EpiLogits><<<dim3(S / 128, S / 128, BH), 256, SM_BIG>>>(
        Qhi, Qlo, Khi, Klo, DK, (size_t)S * DK, (size_t)S * DK, EpiLogits{attn});

    // 3) combine partials -> per-row (max, 1/sum)
    rowreduce<<<(unsigned)((size_t)BH * S * 32 / 256), 256>>>(pm, ps, rm, ri);

    // 4) PV: fused softmax (writes probs into attn) + values GEMM, fully pipelined
    gemm_pv<<<dim3(1, S / 128, BH), 256, SM_PV>>>(attn, rm, ri, Vthi, Vtlo);

    // 5) output projection
    gemm_async<128, 128, EpiOut><<<dim3(E / 128, M_TOK / 128, 1), 256, SM_BIG>>>(
        Vh, Vl, Woh, Wol, E, 0, 0, EpiOut{bout, out});
}

// round 9
// speedup vs baseline: 1.5273x; 1.3594x over previous
#include <cuda_runtime.h>
#include <cuda_fp16.h>
#include <mma.h>
#include <cstdint>
#include <cstddef>
#include <math_constants.h>

using namespace nvcuda;

// Problem constants
static constexpr int B  = 4;
static constexpr int S  = 2048;
static constexpr int E  = 1024;
static constexpr int H  = 16;
static constexpr int DK = 64;
static constexpr int BH = B * H;      // 64
static constexpr int M_TOK = B * S;   // 8192

// ---------------- scratch (device globals; no cudaMalloc allowed) ----------------
// A-side operands: split fp16 (hi/lo). B-side operands: single fp16.
__device__ __half g_xhi[(size_t)M_TOK * E], g_xlo[(size_t)M_TOK * E];
__device__ __half g_Wqt[(size_t)3 * E * E];
__device__ __half g_Wot[(size_t)E * E];
__device__ __half g_Qhi[(size_t)BH * S * DK], g_Qlo[(size_t)BH * S * DK];
__device__ __half g_K  [(size_t)BH * S * DK];
__device__ __half g_Vt [(size_t)BH * DK * S];
__device__ __half g_valshi[(size_t)M_TOK * E], g_valslo[(size_t)M_TOK * E];
// softmax partials: per (bh, row, 128-col block)
__device__ float g_pm[(size_t)BH * S * 16], g_ps[(size_t)BH * S * 16];
__device__ float g_rm[(size_t)BH * S],      g_ri[(size_t)BH * S];

// ---------------- helpers ----------------
__device__ __forceinline__ uint32_t smem_to_u32(const void* p) {
    uint32_t a;
    asm("{ .reg .u64 t; cvta.to.shared.u64 t, %1; cvt.u32.u64 %0, t; }" : "=r"(a) : "l"(p));
    return a;
}
__device__ __forceinline__ void cp_async16(uint32_t dst, const void* src) {
    asm volatile("cp.async.cg.shared.global [%0], [%1], 16;" :: "r"(dst), "l"(src));
}
#define CP_COMMIT() asm volatile("cp.async.commit_group;" ::: "memory")
#define CP_WAIT(N)  asm volatile("cp.async.wait_group %0;" :: "n"(N) : "memory")

__device__ __forceinline__ uint32_t pack2h(float a, float b) {
    __half2 p(__float2half(a), __float2half(b));
    return *reinterpret_cast<uint32_t*>(&p);
}
__device__ __forceinline__ void split2h(float v, __half& h, __half& l) {
    h = __float2half(v);
    l = __float2half(v - __half2float(h));
}
__device__ __forceinline__ void pack_split2h(float a, float b, uint32_t& hi, uint32_t& lo) {
    __half ha, la, hb, lb;
    split2h(a, ha, la); split2h(b, hb, lb);
    __half2 Hp(ha, hb), Lp(la, lb);
    hi = *reinterpret_cast<uint32_t*>(&Hp);
    lo = *reinterpret_cast<uint32_t*>(&Lp);
}

// ---------------- epilogues for projection GEMMs (BN=128, LDC=136) ----------------
struct EpiQKV {
    const float* bias;
    __device__ void run(int /*z*/, int m0, int n0, int tid, const float* Cs) const {
        #pragma unroll
        for (int it = 0; it < 16; it++) {
            int idx = it * 256 + tid;
            int r = idx >> 5;
            int c4 = (idx & 31) * 4;
            float4 v = *reinterpret_cast<const float4*>(Cs + r * 136 + c4);
            int c = n0 + c4;
            v.x += bias[c]; v.y += bias[c + 1]; v.z += bias[c + 2]; v.w += bias[c + 3];
            int h = c / 192, cc = c - h * 192;
            int t = cc >> 6, d0 = cc & 63;
            int gr = m0 + r;
            int b = gr >> 11, s = gr & 2047;
            int bh = b * H + h;
            if (t == 2) {
                // V^T single fp16, scattered along d (stride S)
                float vv[4] = {v.x, v.y, v.z, v.w};
                #pragma unroll
                for (int i = 0; i < 4; i++)
                    g_Vt[((size_t)bh * DK + d0 + i) * S + s] = __float2half(vv[i]);
            } else if (t == 1) {
                // K single fp16
                size_t off = ((size_t)bh * S + s) * DK + d0;
                *reinterpret_cast<uint2*>(g_K + off) =
                    make_uint2(pack2h(v.x, v.y), pack2h(v.z, v.w));
            } else {
                // Q split fp16
                uint32_t h0, l0, h1, l1;
                pack_split2h(v.x, v.y, h0, l0);
                pack_split2h(v.z, v.w, h1, l1);
                size_t off = ((size_t)bh * S + s) * DK + d0;
                *reinterpret_cast<uint2*>(g_Qhi + off) = make_uint2(h0, h1);
                *reinterpret_cast<uint2*>(g_Qlo + off) = make_uint2(l0, l1);
            }
        }
    }
};

struct EpiLogits {
    float* attn;
    __device__ void run(int z, int m0, int n0, int tid, const float* Cs) const {
        float* dst = attn + (size_t)z * S * S;
        const int lane = tid & 31;
        const int nb = n0 >> 7;
        #pragma unroll
        for (int it = 0; it < 16; it++) {
            int idx = it * 256 + tid;
            int r = idx >> 5;          // warp covers one full 128-col row segment
            int c4 = lane * 4;
            float4 v = *reinterpret_cast<const float4*>(Cs + r * 136 + c4);
            v.x *= 0.125f; v.y *= 0.125f; v.z *= 0.125f; v.w *= 0.125f;
            *reinterpret_cast<float4*>(dst + (size_t)(m0 + r) * S + n0 + c4) = v;
            float tm = fmaxf(fmaxf(v.x, v.y), fmaxf(v.z, v.w));
            #pragma unroll
            for (int o = 16; o > 0; o >>= 1) tm = fmaxf(tm, __shfl_xor_sync(0xFFFFFFFFu, tm, o));
            float ts = __expf(v.x - tm) + __expf(v.y - tm) + __expf(v.z - tm) + __expf(v.w - tm);
            #pragma unroll
            for (int o = 16; o > 0; o >>= 1) ts += __shfl_xor_sync(0xFFFFFFFFu, ts, o);
            if (lane == 0) {
                size_t pi = ((size_t)z * S + m0 + r) * 16 + nb;
                g_pm[pi] = tm;
                g_ps[pi] = ts;
            }
        }
    }
};

struct EpiOut {
    const float* bias;
    float* out;
    __device__ void run(int /*z*/, int m0, int n0, int tid, const float* Cs) const {
        #pragma unroll
        for (int it = 0; it < 16; it++) {
            int idx = it * 256 + tid;
            int r = idx >> 5;
            int c4 = (idx & 31) * 4;
            float4 v = *reinterpret_cast<const float4*>(Cs + r * 136 + c4);
            int c = n0 + c4;
            v.x += bias[c]; v.y += bias[c + 1]; v.z += bias[c + 2]; v.w += bias[c + 3];
            *reinterpret_cast<float4*>(out + (size_t)(m0 + r) * E + c) = v;
        }
    }
};

// ---------------- cp.async pipelined fp16 2-pass WMMA GEMM (BK=32, 2 CTAs/SM) -----
// D[M,N] = (Ahi + Alo)[M,K] * B[N,K]^T ; fp32 accum. B rounded to single fp16.
template<int BM, int BN, class Epi>
__global__ void __launch_bounds__(256, 2)
gemm_async(const __half* __restrict__ Ahi, const __half* __restrict__ Alo,
           const __half* __restrict__ Bs, int K, size_t sAz, size_t sBz, Epi epi)
{
    constexpr int LD = 40;                          // BK=32 + 8 pad
    constexpr int STG_BYTES = (2 * BM + BN) * LD * 2;
    constexpr int WM = 32, WN = BN / 2;
    constexpr int MI = WM / 16, NI = WN / 16;
    constexpr int LDC = BN + 8;

    extern __shared__ char smem[];
    const uint32_t sbase = smem_to_u32(smem);
    const int tid = threadIdx.x, wid = tid >> 5;
    const int z = blockIdx.z;
    const int m0 = blockIdx.y * BM, n0 = blockIdx.x * BN;
    const int wm0 = (wid & 3) * WM, wn0 = (wid >> 2) * WN;

    Ahi += (size_t)z * sAz; Alo += (size_t)z * sAz;
    Bs  += (size_t)z * sBz;

    const int nchunks = K >> 5;

    auto stage = [&](int s, int ch) {
        const int k0 = ch << 5;
        const uint32_t sA = sbase + s * STG_BYTES;
        const uint32_t sB = sA + 2 * BM * LD * 2;
        for (int u = tid; u < BM * 4; u += 256) {
            int r = u >> 2, g = u & 3;
            size_t gi = (size_t)(m0 + r) * K + k0 + g * 8;
            uint32_t so = sA + (uint32_t)(r * LD + g * 8) * 2;
            cp_async16(so, Ahi + gi);
            cp_async16(so + BM * LD * 2, Alo + gi);
        }
        for (int u = tid; u < BN * 4; u += 256) {
            int r = u >> 2, g = u & 3;
            size_t gi = (size_t)(n0 + r) * K + k0 + g * 8;
            cp_async16(sB + (uint32_t)(r * LD + g * 8) * 2, Bs + gi);
        }
        CP_COMMIT();
    };

    wmma::fragment<wmma::accumulator, 16, 16, 16, float> acc[MI][NI];
    #pragma unroll
    for (int mi = 0; mi < MI; mi++)
        #pragma unroll
        for (int ni = 0; ni < NI; ni++) wmma::fill_fragment(acc[mi][ni], 0.0f);

    stage(0, 0);
    for (int ch = 0; ch < nchunks; ch++) {
        if (ch + 1 < nchunks) { stage((ch + 1) & 1, ch + 1); CP_WAIT(1); }
        else                  { CP_WAIT(0); }
        __syncthreads();

        const __half* As_hi =
            reinterpret_cast<const __half*>(smem + (ch & 1) * STG_BYTES);
        const __half* As_lo = As_hi + BM * LD;
        const __half* Bs_s  = As_lo + BM * LD;

        #pragma unroll
        for (int ks = 0; ks < 2; ks++) {
            wmma::fragment<wmma::matrix_a, 16, 16, 16, __half, wmma::row_major> ah[MI], al[MI];
            wmma::fragment<wmma::matrix_b, 16, 16, 16, __half, wmma::col_major> bf[NI];
            #pragma unroll
            for (int mi = 0; mi < MI; mi++) {
                wmma::load_matrix_sync(ah[mi], As_hi + (wm0 + mi * 16) * LD + ks * 16, LD);
                wmma::load_matrix_sync(al[mi], As_lo + (wm0 + mi * 16) * LD + ks * 16, LD);
            }
            #pragma unroll
            for (int ni = 0; ni < NI; ni++)
                wmma::load_matrix_sync(bf[ni], Bs_s + (wn0 + ni * 16) * LD + ks * 16, LD);
            #pragma unroll
            for (int mi = 0; mi < MI; mi++)
                #pragma unroll
                for (int ni = 0; ni < NI; ni++) {
                    wmma::mma_sync(acc[mi][ni], ah[mi], bf[ni], acc[mi][ni]);
                    wmma::mma_sync(acc[mi][ni], al[mi], bf[ni], acc[mi][ni]);
                }
        }
        __syncthreads();
    }

    float* Cs = reinterpret_cast<float*>(smem);
    #pragma unroll
    for (int mi = 0; mi < MI; mi++)
        #pragma unroll
        for (int ni = 0; ni < NI; ni++)
            wmma::store_matrix_sync(Cs + (wm0 + mi * 16) * LDC + wn0 + ni * 16,
                                    acc[mi][ni], LDC, wmma::mem_row_major);
    __syncthreads();
    epi.run(z, m0, n0, tid, Cs);
}

// ---------------- combine per-block softmax partials into per-row (m, 1/sum) -----
__global__ void __launch_bounds__(256)
rowreduce(const float* __restrict__ pm, const float* __restrict__ ps,
          float* __restrict__ rm, float* __restrict__ ri)
{
    int w = (blockIdx.x * 256 + threadIdx.x) >> 5;   // one warp per row
    int lane = threadIdx.x & 31;
    float m = -CUDART_INF_F, s = 0.0f;
    if (lane < 16) {
        m = pm[(size_t)w * 16 + lane];
        s = ps[(size_t)w * 16 + lane];
    }
    float gm = m;
    #pragma unroll
    for (int o = 16; o > 0; o >>= 1) gm = fmaxf(gm, __shfl_xor_sync(0xFFFFFFFFu, gm, o));
    float c = (lane < 16) ? s * __expf(m - gm) : 0.0f;
    #pragma unroll
    for (int o = 16; o > 0; o >>= 1) c += __shfl_xor_sync(0xFFFFFFFFu, c, o);
    if (lane == 0) {
        rm[w] = gm;
        ri[w] = 1.0f / c;
    }
}

// ---------------- PV kernel: softmax+probs+PV, fully double-buffered, fp16 2-pass --
__global__ void __launch_bounds__(256, 2)
gemm_pv(float* __restrict__ attn, const float* __restrict__ rm, const float* __restrict__ ri,
        const __half* __restrict__ Vt)
{
    constexpr int BM = 128, LDA = 72, LDV = 80, LDC = 72;
    constexpr int MI = 2, NI = 2;
    constexpr int A_STG = 2 * BM * LDA * 2;        // hi+lo per buffer = 36864
    constexpr int OFF_A = 0;                       // 2 buffers: 73728
    constexpr int OFF_V = 73728;                   // 2 stages * 10240
    constexpr int V_STG = 10240;
    constexpr int NC = S / 64;                     // 32 chunks

    extern __shared__ char smem[];
    const uint32_t sbase = smem_to_u32(smem);
    const int tid = threadIdx.x, wid = tid >> 5;
    const int z = blockIdx.z;
    const int m0 = blockIdx.y * BM;
    const int wm0 = (wid & 3) * 32, wn0 = (wid >> 2) * 32;

    float* A = attn + (size_t)z * S * S;
    const __half* Bv = Vt + (size_t)z * DK * S;

    auto stage_v = [&](int s, int ch) {
        int k0 = ch << 6;
        for (int u = tid; u < 64 * 8; u += 256) {
            int r = u >> 3, g = u & 7;
            cp_async16(sbase + OFF_V + s * V_STG + (uint32_t)(r * LDV + g * 8) * 2,
                       Bv + (size_t)r * S + k0 + g * 8);
        }
        CP_COMMIT();
    };

    auto transform = [&](int s, int ch) {
        const int k0 = ch << 6;
        __half* Ash = reinterpret_cast<__half*>(smem + OFF_A + s * A_STG);
        __half* Asl = Ash + BM * LDA;
        for (int u = tid; u < BM * 8; u += 256) {
            int r = u >> 3, g = u & 7;
            size_t rowoff = (size_t)z * S + m0 + r;
            float m = rm[rowoff], rv = ri[rowoff];
            float* src = A + (size_t)(m0 + r) * S + k0 + g * 8;
            float4 v0 = *reinterpret_cast<const float4*>(src);
            float4 v1 = *reinterpret_cast<const float4*>(src + 4);
            v0.x = __expf(v0.x - m) * rv; v0.y = __expf(v0.y - m) * rv;
            v0.z = __expf(v0.z - m) * rv; v0.w = __expf(v0.w - m) * rv;
            v1.x = __expf(v1.x - m) * rv; v1.y = __expf(v1.y - m) * rv;
            v1.z = __expf(v1.z - m) * rv; v1.w = __expf(v1.w - m) * rv;
            *reinterpret_cast<float4*>(src)     = v0;
            *reinterpret_cast<float4*>(src + 4) = v1;
            uint32_t h0, l0, h1, l1, h2, l2, h3, l3;
            pack_split2h(v0.x, v0.y, h0, l0);
            pack_split2h(v0.z, v0.w, h1, l1);
            pack_split2h(v1.x, v1.y, h2, l2);
            pack_split2h(v1.z, v1.w, h3, l3);
            *reinterpret_cast<uint4*>(Ash + r * LDA + g * 8) = make_uint4(h0, h1, h2, h3);
            *reinterpret_cast<uint4*>(Asl + r * LDA + g * 8) = make_uint4(l0, l1, l2, l3);
        }
    };

    wmma::fragment<wmma::accumulator, 16, 16, 16, float> acc[MI][NI];
    #pragma unroll
    for (int mi = 0; mi < MI; mi++)
        #pragma unroll
        for (int ni = 0; ni < NI; ni++) wmma::fill_fragment(acc[mi][ni], 0.0f);

    stage_v(0, 0);
    transform(0, 0);

    for (int ch = 0; ch < NC; ch++) {
        __syncthreads();

        if (ch + 1 < NC) {
            stage_v((ch + 1) & 1, ch + 1);
            transform((ch + 1) & 1, ch + 1);
            CP_WAIT(1);
        } else {
            CP_WAIT(0);
        }

        const __half* Ash =
            reinterpret_cast<const __half*>(smem + OFF_A + (ch & 1) * A_STG);
        const __half* Asl = Ash + BM * LDA;
        const __half* Bsv =
            reinterpret_cast<const __half*>(smem + OFF_V + (ch & 1) * V_STG);

        #pragma unroll
        for (int ks = 0; ks < 4; ks++) {
            wmma::fragment<wmma::matrix_a, 16, 16, 16, __half, wmma::row_major> ah[MI], al[MI];
            wmma::fragment<wmma::matrix_b, 16, 16, 16, __half, wmma::col_major> bf[NI];
            #pragma unroll
            for (int mi = 0; mi < MI; mi++) {
                wmma::load_matrix_sync(ah[mi], Ash + (wm0 + mi * 16) * LDA + ks * 16, LDA);
                wmma::load_matrix_sync(al[mi], Asl + (wm0 + mi * 16) * LDA + ks * 16, LDA);
            }
            #pragma unroll
            for (int ni = 0; ni < NI; ni++)
                wmma::load_matrix_sync(bf[ni], Bsv + (wn0 + ni * 16) * LDV + ks * 16, LDV);
            #pragma unroll
            for (int mi = 0; mi < MI; mi++)
                #pragma unroll
                for (int ni = 0; ni < NI; ni++) {
                    wmma::mma_sync(acc[mi][ni], ah[mi], bf[ni], acc[mi][ni]);
                    wmma::mma_sync(acc[mi][ni], al[mi], bf[ni], acc[mi][ni]);
                }
        }
    }
    __syncthreads();

    float* Cs = reinterpret_cast<float*>(smem);
    #pragma unroll
    for (int mi = 0; mi < MI; mi++)
        #pragma unroll
        for (int ni = 0; ni < NI; ni++)
            wmma::store_matrix_sync(Cs + (wm0 + mi * 16) * LDC + wn0 + ni * 16,
                                    acc[mi][ni], LDC, wmma::mem_row_major);
    __syncthreads();

    int b = z >> 4, h = z & 15;
    #pragma unroll
    for (int it = 0; it < 8; it++) {
        int idx = it * 256 + tid;
        int r = idx >> 4;
        int c4 = (idx & 15) * 4;
        float4 v = *reinterpret_cast<const float4*>(Cs + r * LDC + c4);
        uint32_t h0, l0, h1, l1;
        pack_split2h(v.x, v.y, h0, l0);
        pack_split2h(v.z, v.w, h1, l1);
        size_t off = (size_t)(b * S + m0 + r) * E + h * DK + c4;
        *reinterpret_cast<uint2*>(g_valshi + off) = make_uint2(h0, h1);
        *reinterpret_cast<uint2*>(g_valslo + off) = make_uint2(l0, l1);
    }
}

// ---------------- pre-kernels ----------------
__global__ void __launch_bounds__(256)
split_kernel(const float* __restrict__ src, __half* __restrict__ dh,
             __half* __restrict__ dl, size_t n)
{
    size_t i = ((size_t)blockIdx.x * 256 + threadIdx.x) * 4;
    if (i >= n) return;
    float4 v = *reinterpret_cast<const float4*>(src + i);
    uint32_t h0, l0, h1, l1;
    pack_split2h(v.x, v.y, h0, l0);
    pack_split2h(v.z, v.w, h1, l1);
    *reinterpret_cast<uint2*>(dh + i) = make_uint2(h0, h1);
    *reinterpret_cast<uint2*>(dl + i) = make_uint2(l0, l1);
}

// W[R][C] -> T[C][R], single fp16
__global__ void __launch_bounds__(256)
transpose_h(const float* __restrict__ W, __half* __restrict__ Th, int R, int C)
{
    __shared__ float t[32][33];
    int c0 = blockIdx.x * 32, r0 = blockIdx.y * 32;
    int tx = threadIdx.x & 31, ty = threadIdx.x >> 5;
    for (int j = ty; j < 32; j += 8)
        t[j][tx] = W[(size_t)(r0 + j) * C + c0 + tx];
    __syncthreads();
    for (int j = ty; j < 32; j += 8)
        Th[(size_t)(c0 + j) * R + r0 + tx] = __float2half(t[tx][j]);
}

// ---------------- launch ----------------
extern "C" void kernel_launch(void* const* d_in, const int* /*in_sizes*/, int /*n_in*/,
                              void* d_out, int /*out_size*/)
{
    const float* x    = (const float*)d_in[0];
    const float* Wqkv = (const float*)d_in[1];
    const float* bqkv = (const float*)d_in[2];
    const float* Wout = (const float*)d_in[3];
    const float* bout = (const float*)d_in[4];

    float* out  = (float*)d_out;
    float* attn = out + (size_t)M_TOK * E;

    __half *xhi, *xlo, *Wq, *Wo, *Qhi, *Qlo, *Kp, *Vt, *Vh, *Vl;
    float *pm, *ps, *rm, *ri;
    cudaGetSymbolAddress((void**)&xhi, g_xhi);
    cudaGetSymbolAddress((void**)&xlo, g_xlo);
    cudaGetSymbolAddress((void**)&Wq,  g_Wqt);
    cudaGetSymbolAddress((void**)&Wo,  g_Wot);
    cudaGetSymbolAddress((void**)&Qhi, g_Qhi);
    cudaGetSymbolAddress((void**)&Qlo, g_Qlo);
    cudaGetSymbolAddress((void**)&Kp,  g_K);
    cudaGetSymbolAddress((void**)&Vt,  g_Vt);
    cudaGetSymbolAddress((void**)&Vh,  g_valshi);
    cudaGetSymbolAddress((void**)&Vl,  g_valslo);
    cudaGetSymbolAddress((void**)&pm,  g_pm);
    cudaGetSymbolAddress((void**)&ps,  g_ps);
    cudaGetSymbolAddress((void**)&rm,  g_rm);
    cudaGetSymbolAddress((void**)&ri,  g_ri);

    // gemm_async smem: max(2 stages * 30720 = 61440, Cs = 128*136*4 = 69632)
    constexpr int SM_BIG = 69632;
    constexpr int SM_PV  = 73728 + 2 * 10240;   // 94208
    cudaFuncSetAttribute(gemm_async<128, 128, EpiQKV>,
                         cudaFuncAttributeMaxDynamicSharedMemorySize, SM_BIG);
    cudaFuncSetAttribute(gemm_async<128, 128, EpiLogits>,
                         cudaFuncAttributeMaxDynamicSharedMemorySize, SM_BIG);
    cudaFuncSetAttribute(gemm_async<128, 128, EpiOut>,
                         cudaFuncAttributeMaxDynamicSharedMemorySize, SM_BIG);
    cudaFuncSetAttribute(gemm_pv,
                         cudaFuncAttributeMaxDynamicSharedMemorySize, SM_PV);

    // 0) operand prep
    transpose_h<<<dim3(3 * E / 32, E / 32), 256>>>(Wqkv, Wq, E, 3 * E);
    transpose_h<<<dim3(E / 32, E / 32), 256>>>(Wout, Wo, E, E);
    split_kernel<<<(unsigned)((size_t)M_TOK * E / 4 / 256), 256>>>(x, xhi, xlo, (size_t)M_TOK * E);

    // 1) QKV projection -> split/single scatter into Q/K/Vt
    gemm_async<128, 128, EpiQKV><<<dim3(3 * E / 128, M_TOK / 128, 1), 256, SM_BIG>>>(
        xhi, xlo, Wq, E, 0, 0, EpiQKV{bqkv});

    // 2) logits = Q*K^T/8 -> attn (raw), plus per-block softmax partials
    gemm_async<128, 128, EpiLogits><<<dim3(S / 128, S / 128, BH), 256, SM_BIG>>>(
        Qhi, Qlo, Kp, DK, (size_t)S * DK, (size_t)S * DK, EpiLogits{attn});

    // 3) combine partials -> per-row (max, 1/sum)
    rowreduce<<<(unsigned)((size_t)BH * S * 32 / 256), 256>>>(pm, ps, rm, ri);

    // 4) PV: fused softmax (writes probs into attn) + values GEMM
    gemm_pv<<<dim3(1, S / 128, BH), 256, SM_PV>>>(attn, rm, ri, Vt);

    // 5) output projection
    gemm_async<128, 128, EpiOut><<<dim3(E / 128, M_TOK / 128, 1), 256, SM_BIG>>>(
        Vh, Vl, Wo, E, 0, 0, EpiOut{bout, out});
}

// round 11
// speedup vs baseline: 1.7229x; 1.1281x over previous
#include <cuda_runtime.h>
#include <cuda_fp16.h>
#include <mma.h>
#include <cstdint>
#include <cstddef>
#include <math_constants.h>

using namespace nvcuda;

// Problem constants
static constexpr int B  = 4;
static constexpr int S  = 2048;
static constexpr int E  = 1024;
static constexpr int H  = 16;
static constexpr int DK = 64;
static constexpr int BH = B * H;      // 64
static constexpr int M_TOK = B * S;   // 8192

// ---------------- scratch (device globals; no cudaMalloc allowed) ----------------
__device__ __half g_xhi[(size_t)M_TOK * E], g_xlo[(size_t)M_TOK * E];
__device__ __half g_Wqt[(size_t)3 * E * E];
__device__ __half g_Wot[(size_t)E * E];
__device__ __half g_Qhi[(size_t)BH * S * DK], g_Qlo[(size_t)BH * S * DK];
__device__ __half g_K  [(size_t)BH * S * DK];
__device__ __half g_Vt [(size_t)BH * DK * S];
__device__ __half g_valshi[(size_t)M_TOK * E], g_valslo[(size_t)M_TOK * E];
__device__ float g_rm[(size_t)BH * S], g_ri[(size_t)BH * S];

// ---------------- helpers ----------------
__device__ __forceinline__ uint32_t smem_to_u32(const void* p) {
    uint32_t a;
    asm("{ .reg .u64 t; cvta.to.shared.u64 t, %1; cvt.u32.u64 %0, t; }" : "=r"(a) : "l"(p));
    return a;
}
__device__ __forceinline__ void cp_async16(uint32_t dst, const void* src) {
    asm volatile("cp.async.cg.shared.global [%0], [%1], 16;" :: "r"(dst), "l"(src));
}
#define CP_COMMIT() asm volatile("cp.async.commit_group;" ::: "memory")
#define CP_WAIT(N)  asm volatile("cp.async.wait_group %0;" :: "n"(N) : "memory")

__device__ __forceinline__ uint32_t pack2h(float a, float b) {
    __half2 p(__float2half(a), __float2half(b));
    return *reinterpret_cast<uint32_t*>(&p);
}
__device__ __forceinline__ void split2h(float v, __half& h, __half& l) {
    h = __float2half(v);
    l = __float2half(v - __half2float(h));
}
__device__ __forceinline__ void pack_split2h(float a, float b, uint32_t& hi, uint32_t& lo) {
    __half ha, la, hb, lb;
    split2h(a, ha, la); split2h(b, hb, lb);
    __half2 Hp(ha, hb), Lp(la, lb);
    hi = *reinterpret_cast<uint32_t*>(&Hp);
    lo = *reinterpret_cast<uint32_t*>(&Lp);
}

// ---------------- epilogues for projection GEMMs (BN=128, LDC=136) ----------------
struct EpiQKV {
    const float* bias;
    __device__ void run(int /*z*/, int m0, int n0, int tid, const float* Cs) const {
        #pragma unroll
        for (int it = 0; it < 16; it++) {
            int idx = it * 256 + tid;
            int r = idx >> 5;
            int c4 = (idx & 31) * 4;
            float4 v = *reinterpret_cast<const float4*>(Cs + r * 136 + c4);
            int c = n0 + c4;
            v.x += bias[c]; v.y += bias[c + 1]; v.z += bias[c + 2]; v.w += bias[c + 3];
            int h = c / 192, cc = c - h * 192;
            int t = cc >> 6, d0 = cc & 63;
            int gr = m0 + r;
            int b = gr >> 11, s = gr & 2047;
            int bh = b * H + h;
            if (t == 2) {
                float vv[4] = {v.x, v.y, v.z, v.w};
                #pragma unroll
                for (int i = 0; i < 4; i++)
                    g_Vt[((size_t)bh * DK + d0 + i) * S + s] = __float2half(vv[i]);
            } else if (t == 1) {
                size_t off = ((size_t)bh * S + s) * DK + d0;
                *reinterpret_cast<uint2*>(g_K + off) =
                    make_uint2(pack2h(v.x, v.y), pack2h(v.z, v.w));
            } else {
                uint32_t h0, l0, h1, l1;
                pack_split2h(v.x, v.y, h0, l0);
                pack_split2h(v.z, v.w, h1, l1);
                size_t off = ((size_t)bh * S + s) * DK + d0;
                *reinterpret_cast<uint2*>(g_Qhi + off) = make_uint2(h0, h1);
                *reinterpret_cast<uint2*>(g_Qlo + off) = make_uint2(l0, l1);
            }
        }
    }
};

struct EpiOut {
    const float* bias;
    float* out;
    __device__ void run(int /*z*/, int m0, int n0, int tid, const float* Cs) const {
        #pragma unroll
        for (int it = 0; it < 16; it++) {
            int idx = it * 256 + tid;
            int r = idx >> 5;
            int c4 = (idx & 31) * 4;
            float4 v = *reinterpret_cast<const float4*>(Cs + r * 136 + c4);
            int c = n0 + c4;
            v.x += bias[c]; v.y += bias[c + 1]; v.z += bias[c + 2]; v.w += bias[c + 3];
            *reinterpret_cast<float4*>(out + (size_t)(m0 + r) * E + c) = v;
        }
    }
};

// ---------------- cp.async pipelined fp16 2-pass WMMA GEMM (BK=32, 2 CTAs/SM) -----
template<int BM, int BN, class Epi>
__global__ void __launch_bounds__(256, 2)
gemm_async(const __half* __restrict__ Ahi, const __half* __restrict__ Alo,
           const __half* __restrict__ Bs, int K, size_t sAz, size_t sBz, Epi epi)
{
    constexpr int LD = 40;
    constexpr int STG_BYTES = (2 * BM + BN) * LD * 2;
    constexpr int WM = 32, WN = BN / 2;
    constexpr int MI = WM / 16, NI = WN / 16;
    constexpr int LDC = BN + 8;

    extern __shared__ char smem[];
    const uint32_t sbase = smem_to_u32(smem);
    const int tid = threadIdx.x, wid = tid >> 5;
    const int z = blockIdx.z;
    const int m0 = blockIdx.y * BM, n0 = blockIdx.x * BN;
    const int wm0 = (wid & 3) * WM, wn0 = (wid >> 2) * WN;

    Ahi += (size_t)z * sAz; Alo += (size_t)z * sAz;
    Bs  += (size_t)z * sBz;

    const int nchunks = K >> 5;

    auto stage = [&](int s, int ch) {
        const int k0 = ch << 5;
        const uint32_t sA = sbase + s * STG_BYTES;
        const uint32_t sB = sA + 2 * BM * LD * 2;
        for (int u = tid; u < BM * 4; u += 256) {
            int r = u >> 2, g = u & 3;
            size_t gi = (size_t)(m0 + r) * K + k0 + g * 8;
            uint32_t so = sA + (uint32_t)(r * LD + g * 8) * 2;
            cp_async16(so, Ahi + gi);
            cp_async16(so + BM * LD * 2, Alo + gi);
        }
        for (int u = tid; u < BN * 4; u += 256) {
            int r = u >> 2, g = u & 3;
            size_t gi = (size_t)(n0 + r) * K + k0 + g * 8;
            cp_async16(sB + (uint32_t)(r * LD + g * 8) * 2, Bs + gi);
        }
        CP_COMMIT();
    };

    wmma::fragment<wmma::accumulator, 16, 16, 16, float> acc[MI][NI];
    #pragma unroll
    for (int mi = 0; mi < MI; mi++)
        #pragma unroll
        for (int ni = 0; ni < NI; ni++) wmma::fill_fragment(acc[mi][ni], 0.0f);

    stage(0, 0);
    for (int ch = 0; ch < nchunks; ch++) {
        if (ch + 1 < nchunks) { stage((ch + 1) & 1, ch + 1); CP_WAIT(1); }
        else                  { CP_WAIT(0); }
        __syncthreads();

        const __half* As_hi =
            reinterpret_cast<const __half*>(smem + (ch & 1) * STG_BYTES);
        const __half* As_lo = As_hi + BM * LD;
        const __half* Bs_s  = As_lo + BM * LD;

        #pragma unroll
        for (int ks = 0; ks < 2; ks++) {
            wmma::fragment<wmma::matrix_a, 16, 16, 16, __half, wmma::row_major> ah[MI], al[MI];
            wmma::fragment<wmma::matrix_b, 16, 16, 16, __half, wmma::col_major> bf[NI];
            #pragma unroll
            for (int mi = 0; mi < MI; mi++) {
                wmma::load_matrix_sync(ah[mi], As_hi + (wm0 + mi * 16) * LD + ks * 16, LD);
                wmma::load_matrix_sync(al[mi], As_lo + (wm0 + mi * 16) * LD + ks * 16, LD);
            }
            #pragma unroll
            for (int ni = 0; ni < NI; ni++)
                wmma::load_matrix_sync(bf[ni], Bs_s + (wn0 + ni * 16) * LD + ks * 16, LD);
            #pragma unroll
            for (int mi = 0; mi < MI; mi++)
                #pragma unroll
                for (int ni = 0; ni < NI; ni++) {
                    wmma::mma_sync(acc[mi][ni], ah[mi], bf[ni], acc[mi][ni]);
                    wmma::mma_sync(acc[mi][ni], al[mi], bf[ni], acc[mi][ni]);
                }
        }
        __syncthreads();
    }

    float* Cs = reinterpret_cast<float*>(smem);
    #pragma unroll
    for (int mi = 0; mi < MI; mi++)
        #pragma unroll
        for (int ni = 0; ni < NI; ni++)
            wmma::store_matrix_sync(Cs + (wm0 + mi * 16) * LDC + wn0 + ni * 16,
                                    acc[mi][ni], LDC, wmma::mem_row_major);
    __syncthreads();
    epi.run(z, m0, n0, tid, Cs);
}

// ---------------- STATS kernel: exact row (max, 1/sum) without writing logits ------
__global__ void __launch_bounds__(256, 2)
stats_kernel(const __half* __restrict__ Qhi, const __half* __restrict__ Qlo,
             const __half* __restrict__ Kp,
             float* __restrict__ rm, float* __restrict__ ri)
{
    constexpr int LDQ = 72, LDK = 72, LDC = 72;
    constexpr int OFF_Q = 0;       // Qh 18432 + Ql 18432
    constexpr int OFF_K = 36864;   // 2 x 9216
    constexpr int OFF_C = 55296;   // 36864
    constexpr int OFF_M = 92160;   // 512
    constexpr int OFF_S = 92672;   // 512 ; total 93184

    extern __shared__ char smem[];
    const uint32_t sbase = smem_to_u32(smem);
    const int tid = threadIdx.x, wid = tid >> 5;
    const int z = blockIdx.z, m0 = blockIdx.y * 128;
    const int wm0 = (wid & 3) * 32, wn0 = (wid >> 2) * 32;

    const __half* Qh_g = Qhi + ((size_t)z * S + m0) * DK;
    const __half* Ql_g = Qlo + ((size_t)z * S + m0) * DK;
    const __half* K_g  = Kp  + (size_t)z * S * DK;

    for (int u = tid; u < 128 * 8; u += 256) {
        int r = u >> 3, g = u & 7;
        cp_async16(sbase + OFF_Q + (uint32_t)(r * LDQ + g * 8) * 2, Qh_g + (size_t)r * DK + g * 8);
        cp_async16(sbase + OFF_Q + 18432 + (uint32_t)(r * LDQ + g * 8) * 2, Ql_g + (size_t)r * DK + g * 8);
    }
    CP_COMMIT();
    auto stage_k = [&](int s, int ch) {
        int k0 = ch << 6;
        for (int u = tid; u < 64 * 8; u += 256) {
            int r = u >> 3, g = u & 7;
            cp_async16(sbase + OFF_K + s * 9216 + (uint32_t)(r * LDK + g * 8) * 2,
                       K_g + (size_t)(k0 + r) * DK + g * 8);
        }
        CP_COMMIT();
    };
    stage_k(0, 0);

    float* sM = reinterpret_cast<float*>(smem + OFF_M);
    float* sS = reinterpret_cast<float*>(smem + OFF_S);
    if (tid < 128) { sM[tid] = -CUDART_INF_F; sS[tid] = 0.0f; }

    const __half* sQh = reinterpret_cast<const __half*>(smem + OFF_Q);
    const __half* sQl = reinterpret_cast<const __half*>(smem + OFF_Q + 18432);
    float* Cs = reinterpret_cast<float*>(smem + OFF_C);

    for (int ch = 0; ch < 32; ch++) {
        if (ch + 1 < 32) { stage_k((ch + 1) & 1, ch + 1); CP_WAIT(1); }
        else             { CP_WAIT(0); }
        __syncthreads();
        const __half* sK = reinterpret_cast<const __half*>(smem + OFF_K + (ch & 1) * 9216);

        wmma::fragment<wmma::accumulator, 16, 16, 16, float> acc[2][2];
        #pragma unroll
        for (int mi = 0; mi < 2; mi++)
            #pragma unroll
            for (int ni = 0; ni < 2; ni++) wmma::fill_fragment(acc[mi][ni], 0.0f);

        #pragma unroll
        for (int ks = 0; ks < 4; ks++) {
            wmma::fragment<wmma::matrix_a, 16, 16, 16, __half, wmma::row_major> ah[2], al[2];
            wmma::fragment<wmma::matrix_b, 16, 16, 16, __half, wmma::col_major> bf[2];
            #pragma unroll
            for (int mi = 0; mi < 2; mi++) {
                wmma::load_matrix_sync(ah[mi], sQh + (wm0 + mi * 16) * LDQ + ks * 16, LDQ);
                wmma::load_matrix_sync(al[mi], sQl + (wm0 + mi * 16) * LDQ + ks * 16, LDQ);
            }
            #pragma unroll
            for (int ni = 0; ni < 2; ni++)
                wmma::load_matrix_sync(bf[ni], sK + (wn0 + ni * 16) * LDK + ks * 16, LDK);
            #pragma unroll
            for (int mi = 0; mi < 2; mi++)
                #pragma unroll
                for (int ni = 0; ni < 2; ni++) {
                    wmma::mma_sync(acc[mi][ni], ah[mi], bf[ni], acc[mi][ni]);
                    wmma::mma_sync(acc[mi][ni], al[mi], bf[ni], acc[mi][ni]);
                }
        }
        #pragma unroll
        for (int mi = 0; mi < 2; mi++)
            #pragma unroll
            for (int ni = 0; ni < 2; ni++)
                wmma::store_matrix_sync(Cs + (wm0 + mi * 16) * LDC + wn0 + ni * 16,
                                        acc[mi][ni], LDC, wmma::mem_row_major);
        __syncthreads();

        #pragma unroll
        for (int it = 0; it < 8; it++) {
            int idx = it * 256 + tid;
            int r = idx >> 4, c4 = (idx & 15) * 4;
            float4 v = *reinterpret_cast<const float4*>(Cs + r * LDC + c4);
            v.x *= 0.125f; v.y *= 0.125f; v.z *= 0.125f; v.w *= 0.125f;
            float tm = fmaxf(fmaxf(v.x, v.y), fmaxf(v.z, v.w));
            #pragma unroll
            for (int o = 8; o > 0; o >>= 1) tm = fmaxf(tm, __shfl_xor_sync(0xFFFFFFFFu, tm, o));
            float ts = __expf(v.x - tm) + __expf(v.y - tm) + __expf(v.z - tm) + __expf(v.w - tm);
            #pragma unroll
            for (int o = 8; o > 0; o >>= 1) ts += __shfl_xor_sync(0xFFFFFFFFu, ts, o);
            if ((tid & 15) == 0) {
                float om = sM[r], os = sS[r];
                float nm = fmaxf(om, tm);
                sS[r] = os * __expf(om - nm) + ts * __expf(tm - nm);
                sM[r] = nm;
            }
        }
        __syncthreads();
    }

    if (tid < 128) {
        size_t ro = (size_t)z * S + m0 + tid;
        rm[ro] = sM[tid];
        ri[ro] = 1.0f / sS[tid];
    }
}

// ---------------- PV2: recompute QK^T, softmax -> probs (only attn write), PV ------
// RACE FIX vs round 10: __syncthreads() at loop top BEFORE stage_kv(ch+1), so the
// previous iteration's PV MMA (reading KV buffer (ch+1)&1 and Ph) is complete before
// that buffer is overwritten; second sync after CP_WAIT for cross-thread visibility.
__global__ void __launch_bounds__(256, 2)
pv2_kernel(float* __restrict__ attn,
           const float* __restrict__ rm, const float* __restrict__ ri,
           const __half* __restrict__ Qhi, const __half* __restrict__ Qlo,
           const __half* __restrict__ Kp, const __half* __restrict__ Vt)
{
    constexpr int LDQ = 72, LDK = 72, LDV = 72, LDCF = 72, LDP = 144;
    constexpr int OFF_Q  = 0;       // 36864
    constexpr int OFF_K  = 36864;   // 2 x 9216
    constexpr int OFF_V  = 55296;   // 2 x 9216
    constexpr int OFF_C  = 73728;   // 36864 (fp32 logits / fp16 probs overlay)
    constexpr int OFF_RM = 110592;  // 512
    constexpr int OFF_RI = 111104;  // 512 ; total 111616

    extern __shared__ char smem[];
    const uint32_t sbase = smem_to_u32(smem);
    const int tid = threadIdx.x, wid = tid >> 5;
    const int z = blockIdx.z, m0 = blockIdx.y * 128;
    const int wm0 = (wid & 3) * 32, wn0 = (wid >> 2) * 32;

    const __half* Qh_g = Qhi + ((size_t)z * S + m0) * DK;
    const __half* Ql_g = Qlo + ((size_t)z * S + m0) * DK;
    const __half* K_g  = Kp  + (size_t)z * S * DK;
    const __half* V_g  = Vt  + (size_t)z * DK * S;
    float* attnZ = attn + (size_t)z * S * S;

    for (int u = tid; u < 128 * 8; u += 256) {
        int r = u >> 3, g = u & 7;
        cp_async16(sbase + OFF_Q + (uint32_t)(r * LDQ + g * 8) * 2, Qh_g + (size_t)r * DK + g * 8);
        cp_async16(sbase + OFF_Q + 18432 + (uint32_t)(r * LDQ + g * 8) * 2, Ql_g + (size_t)r * DK + g * 8);
    }
    CP_COMMIT();
    auto stage_kv = [&](int s, int ch) {
        int k0 = ch << 6;
        for (int u = tid; u < 64 * 8; u += 256) {
            int r = u >> 3, g = u & 7;
            cp_async16(sbase + OFF_K + s * 9216 + (uint32_t)(r * LDK + g * 8) * 2,
                       K_g + (size_t)(k0 + r) * DK + g * 8);
            cp_async16(sbase + OFF_V + s * 9216 + (uint32_t)(r * LDV + g * 8) * 2,
                       V_g + (size_t)r * S + k0 + g * 8);
        }
        CP_COMMIT();
    };
    stage_kv(0, 0);

    float* sRm = reinterpret_cast<float*>(smem + OFF_RM);
    float* sRi = reinterpret_cast<float*>(smem + OFF_RI);
    if (tid < 128) {
        size_t ro = (size_t)z * S + m0 + tid;
        sRm[tid] = rm[ro];
        sRi[tid] = ri[ro];
    }

    const __half* sQh = reinterpret_cast<const __half*>(smem + OFF_Q);
    const __half* sQl = reinterpret_cast<const __half*>(smem + OFF_Q + 18432);
    float* Csf = reinterpret_cast<float*>(smem + OFF_C);
    __half* Ph = reinterpret_cast<__half*>(smem + OFF_C);

    wmma::fragment<wmma::accumulator, 16, 16, 16, float> pacc[2][2];
    #pragma unroll
    for (int mi = 0; mi < 2; mi++)
        #pragma unroll
        for (int ni = 0; ni < 2; ni++) wmma::fill_fragment(pacc[mi][ni], 0.0f);

    for (int ch = 0; ch < 32; ch++) {
        __syncthreads();   // prev PV MMA complete: KV buf (ch+1)&1 and Ph reusable

        if (ch + 1 < 32) { stage_kv((ch + 1) & 1, ch + 1); CP_WAIT(1); }
        else             { CP_WAIT(0); }
        __syncthreads();   // KV[ch] visible to all threads

        const __half* sK = reinterpret_cast<const __half*>(smem + OFF_K + (ch & 1) * 9216);
        const __half* sV = reinterpret_cast<const __half*>(smem + OFF_V + (ch & 1) * 9216);

        // ---- QK^T recompute (identical arithmetic to stats_kernel) ----
        wmma::fragment<wmma::accumulator, 16, 16, 16, float> qacc[2][2];
        #pragma unroll
        for (int mi = 0; mi < 2; mi++)
            #pragma unroll
            for (int ni = 0; ni < 2; ni++) wmma::fill_fragment(qacc[mi][ni], 0.0f);
        #pragma unroll
        for (int ks = 0; ks < 4; ks++) {
            wmma::fragment<wmma::matrix_a, 16, 16, 16, __half, wmma::row_major> ah[2], al[2];
            wmma::fragment<wmma::matrix_b, 16, 16, 16, __half, wmma::col_major> bf[2];
            #pragma unroll
            for (int mi = 0; mi < 2; mi++) {
                wmma::load_matrix_sync(ah[mi], sQh + (wm0 + mi * 16) * LDQ + ks * 16, LDQ);
                wmma::load_matrix_sync(al[mi], sQl + (wm0 + mi * 16) * LDQ + ks * 16, LDQ);
            }
            #pragma unroll
            for (int ni = 0; ni < 2; ni++)
                wmma::load_matrix_sync(bf[ni], sK + (wn0 + ni * 16) * LDK + ks * 16, LDK);
            #pragma unroll
            for (int mi = 0; mi < 2; mi++)
                #pragma unroll
                for (int ni = 0; ni < 2; ni++) {
                    wmma::mma_sync(qacc[mi][ni], ah[mi], bf[ni], qacc[mi][ni]);
                    wmma::mma_sync(qacc[mi][ni], al[mi], bf[ni], qacc[mi][ni]);
                }
        }
        #pragma unroll
        for (int mi = 0; mi < 2; mi++)
            #pragma unroll
            for (int ni = 0; ni < 2; ni++)
                wmma::store_matrix_sync(Csf + (wm0 + mi * 16) * LDCF + wn0 + ni * 16,
                                        qacc[mi][ni], LDCF, wmma::mem_row_major);
        __syncthreads();

        // ---- transform: exp-normalize, write probs to attn, in-place fp16 split ----
        const int n0 = ch << 6;
        #pragma unroll
        for (int it = 0; it < 8; it++) {
            int idx = it * 256 + tid;
            int r = idx >> 4, c4 = (idx & 15) * 4;
            float4 v = *reinterpret_cast<const float4*>(Csf + r * LDCF + c4);
            float m = sRm[r], rv = sRi[r];
            float4 p;
            p.x = __expf(v.x * 0.125f - m) * rv;
            p.y = __expf(v.y * 0.125f - m) * rv;
            p.z = __expf(v.z * 0.125f - m) * rv;
            p.w = __expf(v.w * 0.125f - m) * rv;
            *reinterpret_cast<float4*>(attnZ + (size_t)(m0 + r) * S + n0 + c4) = p;
            __syncwarp();   // all Csf reads of this warp's rows complete before overlay
            uint32_t h0, l0, h1, l1;
            pack_split2h(p.x, p.y, h0, l0);
            pack_split2h(p.z, p.w, h1, l1);
            *reinterpret_cast<uint2*>(Ph + r * LDP + c4)      = make_uint2(h0, h1);
            *reinterpret_cast<uint2*>(Ph + r * LDP + 72 + c4) = make_uint2(l0, l1);
        }
        __syncthreads();

        // ---- PV MMA (loop-top sync of next iter guards buffer reuse) ----
        #pragma unroll
        for (int ks = 0; ks < 4; ks++) {
            wmma::fragment<wmma::matrix_a, 16, 16, 16, __half, wmma::row_major> ah[2], al[2];
            wmma::fragment<wmma::matrix_b, 16, 16, 16, __half, wmma::col_major> bf[2];
            #pragma unroll
            for (int mi = 0; mi < 2; mi++) {
                wmma::load_matrix_sync(ah[mi], Ph + (wm0 + mi * 16) * LDP + ks * 16, LDP);
                wmma::load_matrix_sync(al[mi], Ph + (wm0 + mi * 16) * LDP + 72 + ks * 16, LDP);
            }
            #pragma unroll
            for (int ni = 0; ni < 2; ni++)
                wmma::load_matrix_sync(bf[ni], sV + (wn0 + ni * 16) * LDV + ks * 16, LDV);
            #pragma unroll
            for (int mi = 0; mi < 2; mi++)
                #pragma unroll
                for (int ni = 0; ni < 2; ni++) {
                    wmma::mma_sync(pacc[mi][ni], ah[mi], bf[ni], pacc[mi][ni]);
                    wmma::mma_sync(pacc[mi][ni], al[mi], bf[ni], pacc[mi][ni]);
                }
        }
    }
    __syncthreads();

    // ---- epilogue: values -> g_vals hi/lo [B,S,E] ----
    #pragma unroll
    for (int mi = 0; mi < 2; mi++)
        #pragma unroll
        for (int ni = 0; ni < 2; ni++)
            wmma::store_matrix_sync(Csf + (wm0 + mi * 16) * 72 + wn0 + ni * 16,
                                    pacc[mi][ni], 72, wmma::mem_row_major);
    __syncthreads();

    int b = z >> 4, h = z & 15;
    #pragma unroll
    for (int it = 0; it < 8; it++) {
        int idx = it * 256 + tid;
        int r = idx >> 4;
        int c4 = (idx & 15) * 4;
        float4 v = *reinterpret_cast<const float4*>(Csf + r * 72 + c4);
        uint32_t h0, l0, h1, l1;
        pack_split2h(v.x, v.y, h0, l0);
        pack_split2h(v.z, v.w, h1, l1);
        size_t off = (size_t)(b * S + m0 + r) * E + h * DK + c4;
        *reinterpret_cast<uint2*>(g_valshi + off) = make_uint2(h0, h1);
        *reinterpret_cast<uint2*>(g_valslo + off) = make_uint2(l0, l1);
    }
}

// ---------------- pre-kernels ----------------
__global__ void __launch_bounds__(256)
split_kernel(const float* __restrict__ src, __half* __restrict__ dh,
             __half* __restrict__ dl, size_t n)
{
    size_t i = ((size_t)blockIdx.x * 256 + threadIdx.x) * 4;
    if (i >= n) return;
    float4 v = *reinterpret_cast<const float4*>(src + i);
    uint32_t h0, l0, h1, l1;
    pack_split2h(v.x, v.y, h0, l0);
    pack_split2h(v.z, v.w, h1, l1);
    *reinterpret_cast<uint2*>(dh + i) = make_uint2(h0, h1);
    *reinterpret_cast<uint2*>(dl + i) = make_uint2(l0, l1);
}

__global__ void __launch_bounds__(256)
transpose_h(const float* __restrict__ W, __half* __restrict__ Th, int R, int C)
{
    __shared__ float t[32][33];
    int c0 = blockIdx.x * 32, r0 = blockIdx.y * 32;
    int tx = threadIdx.x & 31, ty = threadIdx.x >> 5;
    for (int j = ty; j < 32; j += 8)
        t[j][tx] = W[(size_t)(r0 + j) * C + c0 + tx];
    __syncthreads();
    for (int j = ty; j < 32; j += 8)
        Th[(size_t)(c0 + j) * R + r0 + tx] = __float2half(t[tx][j]);
}

// ---------------- launch ----------------
extern "C" void kernel_launch(void* const* d_in, const int* /*in_sizes*/, int /*n_in*/,
                              void* d_out, int /*out_size*/)
{
    const float* x    = (const float*)d_in[0];
    const float* Wqkv = (const float*)d_in[1];
    const float* bqkv = (const float*)d_in[2];
    const float* Wout = (const float*)d_in[3];
    const float* bout = (const float*)d_in[4];

    float* out  = (float*)d_out;
    float* attn = out + (size_t)M_TOK * E;

    __half *xhi, *xlo, *Wq, *Wo, *Qhi, *Qlo, *Kp, *Vt, *Vh, *Vl;
    float *rm, *ri;
    cudaGetSymbolAddress((void**)&xhi, g_xhi);
    cudaGetSymbolAddress((void**)&xlo, g_xlo);
    cudaGetSymbolAddress((void**)&Wq,  g_Wqt);
    cudaGetSymbolAddress((void**)&Wo,  g_Wot);
    cudaGetSymbolAddress((void**)&Qhi, g_Qhi);
    cudaGetSymbolAddress((void**)&Qlo, g_Qlo);
    cudaGetSymbolAddress((void**)&Kp,  g_K);
    cudaGetSymbolAddress((void**)&Vt,  g_Vt);
    cudaGetSymbolAddress((void**)&Vh,  g_valshi);
    cudaGetSymbolAddress((void**)&Vl,  g_valslo);
    cudaGetSymbolAddress((void**)&rm,  g_rm);
    cudaGetSymbolAddress((void**)&ri,  g_ri);

    constexpr int SM_BIG   = 69632;
    constexpr int SM_STATS = 93184;
    constexpr int SM_PV2   = 111616;
    cudaFuncSetAttribute(gemm_async<128, 128, EpiQKV>,
                         cudaFuncAttributeMaxDynamicSharedMemorySize, SM_BIG);
    cudaFuncSetAttribute(gemm_async<128, 128, EpiOut>,
                         cudaFuncAttributeMaxDynamicSharedMemorySize, SM_BIG);
    cudaFuncSetAttribute(stats_kernel,
                         cudaFuncAttributeMaxDynamicSharedMemorySize, SM_STATS);
    cudaFuncSetAttribute(pv2_kernel,
                         cudaFuncAttributeMaxDynamicSharedMemorySize, SM_PV2);

    // 0) operand prep
    transpose_h<<<dim3(3 * E / 32, E / 32), 256>>>(Wqkv, Wq, E, 3 * E);
    transpose_h<<<dim3(E / 32, E / 32), 256>>>(Wout, Wo, E, E);
    split_kernel<<<(unsigned)((size_t)M_TOK * E / 4 / 256), 256>>>(x, xhi, xlo, (size_t)M_TOK * E);

    // 1) QKV projection -> split/single scatter into Q/K/Vt
    gemm_async<128, 128, EpiQKV><<<dim3(3 * E / 128, M_TOK / 128, 1), 256, SM_BIG>>>(
        xhi, xlo, Wq, E, 0, 0, EpiQKV{bqkv});

    // 2) stats: exact per-row (max, 1/sum) — no logits written
    stats_kernel<<<dim3(1, S / 128, BH), 256, SM_STATS>>>(Qhi, Qlo, Kp, rm, ri);

    // 3) PV2: recompute logits, write probs to attn (single pass), PV GEMM
    pv2_kernel<<<dim3(1, S / 128, BH), 256, SM_PV2>>>(attn, rm, ri, Qhi, Qlo, Kp, Vt);

    // 4) output projection
    gemm_async<128, 128, EpiOut><<<dim3(E / 128, M_TOK / 128, 1), 256, SM_BIG>>>(
        Vh, Vl, Wo, E, 0, 0, EpiOut{bout, out});
}

// round 12
// speedup vs baseline: 1.9267x; 1.1183x over previous
#include <cuda_runtime.h>
#include <cuda_fp16.h>
#include <mma.h>
#include <cstdint>
#include <cstddef>
#include <math_constants.h>

using namespace nvcuda;

// Problem constants
static constexpr int B  = 4;
static constexpr int S  = 2048;
static constexpr int E  = 1024;
static constexpr int H  = 16;
static constexpr int DK = 64;
static constexpr int BH = B * H;      // 64
static constexpr int M_TOK = B * S;   // 8192

// ---------------- scratch (device globals; no cudaMalloc allowed) ----------------
__device__ __half g_xhi[(size_t)M_TOK * E], g_xlo[(size_t)M_TOK * E];
__device__ __half g_Wqt[(size_t)3 * E * E];
__device__ __half g_Wot[(size_t)E * E];
__device__ __half g_Qhi[(size_t)BH * S * DK], g_Qlo[(size_t)BH * S * DK];
__device__ __half g_K  [(size_t)BH * S * DK];
__device__ __half g_Vt [(size_t)BH * DK * S];
__device__ __half g_vals[(size_t)M_TOK * E];      // single fp16 now
__device__ float g_rm[(size_t)BH * S], g_ri[(size_t)BH * S];

// ---------------- helpers ----------------
__device__ __forceinline__ uint32_t smem_to_u32(const void* p) {
    uint32_t a;
    asm("{ .reg .u64 t; cvta.to.shared.u64 t, %1; cvt.u32.u64 %0, t; }" : "=r"(a) : "l"(p));
    return a;
}
__device__ __forceinline__ void cp_async16(uint32_t dst, const void* src) {
    asm volatile("cp.async.cg.shared.global [%0], [%1], 16;" :: "r"(dst), "l"(src));
}
#define CP_COMMIT() asm volatile("cp.async.commit_group;" ::: "memory")
#define CP_WAIT(N)  asm volatile("cp.async.wait_group %0;" :: "n"(N) : "memory")

__device__ __forceinline__ uint32_t pack2h(float a, float b) {
    __half2 p(__float2half(a), __float2half(b));
    return *reinterpret_cast<uint32_t*>(&p);
}
__device__ __forceinline__ void split2h(float v, __half& h, __half& l) {
    h = __float2half(v);
    l = __float2half(v - __half2float(h));
}
__device__ __forceinline__ void pack_split2h(float a, float b, uint32_t& hi, uint32_t& lo) {
    __half ha, la, hb, lb;
    split2h(a, ha, la); split2h(b, hb, lb);
    __half2 Hp(ha, hb), Lp(la, lb);
    hi = *reinterpret_cast<uint32_t*>(&Hp);
    lo = *reinterpret_cast<uint32_t*>(&Lp);
}

// ---------------- epilogues for projection GEMMs (BN=128, LDC=136) ----------------
struct EpiQKV {
    const float* bias;
    __device__ void run(int /*z*/, int m0, int n0, int tid, const float* Cs) const {
        #pragma unroll
        for (int it = 0; it < 16; it++) {
            int idx = it * 256 + tid;
            int r = idx >> 5;
            int c4 = (idx & 31) * 4;
            float4 v = *reinterpret_cast<const float4*>(Cs + r * 136 + c4);
            int c = n0 + c4;
            v.x += bias[c]; v.y += bias[c + 1]; v.z += bias[c + 2]; v.w += bias[c + 3];
            int h = c / 192, cc = c - h * 192;
            int t = cc >> 6, d0 = cc & 63;
            int gr = m0 + r;
            int b = gr >> 11, s = gr & 2047;
            int bh = b * H + h;
            if (t == 2) {
                float vv[4] = {v.x, v.y, v.z, v.w};
                #pragma unroll
                for (int i = 0; i < 4; i++)
                    g_Vt[((size_t)bh * DK + d0 + i) * S + s] = __float2half(vv[i]);
            } else if (t == 1) {
                size_t off = ((size_t)bh * S + s) * DK + d0;
                *reinterpret_cast<uint2*>(g_K + off) =
                    make_uint2(pack2h(v.x, v.y), pack2h(v.z, v.w));
            } else {
                uint32_t h0, l0, h1, l1;
                pack_split2h(v.x, v.y, h0, l0);
                pack_split2h(v.z, v.w, h1, l1);
                size_t off = ((size_t)bh * S + s) * DK + d0;
                *reinterpret_cast<uint2*>(g_Qhi + off) = make_uint2(h0, h1);
                *reinterpret_cast<uint2*>(g_Qlo + off) = make_uint2(l0, l1);
            }
        }
    }
};

struct EpiOut {
    const float* bias;
    float* out;
    __device__ void run(int /*z*/, int m0, int n0, int tid, const float* Cs) const {
        #pragma unroll
        for (int it = 0; it < 16; it++) {
            int idx = it * 256 + tid;
            int r = idx >> 5;
            int c4 = (idx & 31) * 4;
            float4 v = *reinterpret_cast<const float4*>(Cs + r * 136 + c4);
            int c = n0 + c4;
            v.x += bias[c]; v.y += bias[c + 1]; v.z += bias[c + 2]; v.w += bias[c + 3];
            *reinterpret_cast<float4*>(out + (size_t)(m0 + r) * E + c) = v;
        }
    }
};

// ---------------- cp.async pipelined fp16 WMMA GEMM (BK=32, 2 CTAs/SM) ------------
// AP=2: A split hi/lo (2 MMA passes). AP=1: A single fp16 (1 pass).
template<int BM, int BN, int AP, class Epi>
__global__ void __launch_bounds__(256, 2)
gemm_async(const __half* __restrict__ Ahi, const __half* __restrict__ Alo,
           const __half* __restrict__ Bs, int K, size_t sAz, size_t sBz, Epi epi)
{
    constexpr int LD = 40;
    constexpr int STG_BYTES = (AP * BM + BN) * LD * 2;
    constexpr int WM = 32, WN = BN / 2;
    constexpr int MI = WM / 16, NI = WN / 16;
    constexpr int LDC = BN + 8;

    extern __shared__ char smem[];
    const uint32_t sbase = smem_to_u32(smem);
    const int tid = threadIdx.x, wid = tid >> 5;
    const int z = blockIdx.z;
    const int m0 = blockIdx.y * BM, n0 = blockIdx.x * BN;
    const int wm0 = (wid & 3) * WM, wn0 = (wid >> 2) * WN;

    Ahi += (size_t)z * sAz;
    if (AP == 2) Alo += (size_t)z * sAz;
    Bs += (size_t)z * sBz;

    const int nchunks = K >> 5;

    auto stage = [&](int s, int ch) {
        const int k0 = ch << 5;
        const uint32_t sA = sbase + s * STG_BYTES;
        const uint32_t sB = sA + AP * BM * LD * 2;
        for (int u = tid; u < BM * 4; u += 256) {
            int r = u >> 2, g = u & 3;
            size_t gi = (size_t)(m0 + r) * K + k0 + g * 8;
            uint32_t so = sA + (uint32_t)(r * LD + g * 8) * 2;
            cp_async16(so, Ahi + gi);
            if (AP == 2) cp_async16(so + BM * LD * 2, Alo + gi);
        }
        for (int u = tid; u < BN * 4; u += 256) {
            int r = u >> 2, g = u & 3;
            size_t gi = (size_t)(n0 + r) * K + k0 + g * 8;
            cp_async16(sB + (uint32_t)(r * LD + g * 8) * 2, Bs + gi);
        }
        CP_COMMIT();
    };

    wmma::fragment<wmma::accumulator, 16, 16, 16, float> acc[MI][NI];
    #pragma unroll
    for (int mi = 0; mi < MI; mi++)
        #pragma unroll
        for (int ni = 0; ni < NI; ni++) wmma::fill_fragment(acc[mi][ni], 0.0f);

    stage(0, 0);
    for (int ch = 0; ch < nchunks; ch++) {
        if (ch + 1 < nchunks) { stage((ch + 1) & 1, ch + 1); CP_WAIT(1); }
        else                  { CP_WAIT(0); }
        __syncthreads();

        const __half* As_hi =
            reinterpret_cast<const __half*>(smem + (ch & 1) * STG_BYTES);
        const __half* As_lo = As_hi + BM * LD;
        const __half* Bs_s  = As_hi + AP * BM * LD;

        #pragma unroll
        for (int ks = 0; ks < 2; ks++) {
            wmma::fragment<wmma::matrix_a, 16, 16, 16, __half, wmma::row_major> ah[MI], al[MI];
            wmma::fragment<wmma::matrix_b, 16, 16, 16, __half, wmma::col_major> bf[NI];
            #pragma unroll
            for (int mi = 0; mi < MI; mi++) {
                wmma::load_matrix_sync(ah[mi], As_hi + (wm0 + mi * 16) * LD + ks * 16, LD);
                if (AP == 2)
                    wmma::load_matrix_sync(al[mi], As_lo + (wm0 + mi * 16) * LD + ks * 16, LD);
            }
            #pragma unroll
            for (int ni = 0; ni < NI; ni++)
                wmma::load_matrix_sync(bf[ni], Bs_s + (wn0 + ni * 16) * LD + ks * 16, LD);
            #pragma unroll
            for (int mi = 0; mi < MI; mi++)
                #pragma unroll
                for (int ni = 0; ni < NI; ni++) {
                    wmma::mma_sync(acc[mi][ni], ah[mi], bf[ni], acc[mi][ni]);
                    if (AP == 2)
                        wmma::mma_sync(acc[mi][ni], al[mi], bf[ni], acc[mi][ni]);
                }
        }
        __syncthreads();
    }

    float* Cs = reinterpret_cast<float*>(smem);
    #pragma unroll
    for (int mi = 0; mi < MI; mi++)
        #pragma unroll
        for (int ni = 0; ni < NI; ni++)
            wmma::store_matrix_sync(Cs + (wm0 + mi * 16) * LDC + wn0 + ni * 16,
                                    acc[mi][ni], LDC, wmma::mem_row_major);
    __syncthreads();
    epi.run(z, m0, n0, tid, Cs);
}

// ---------------- STATS kernel: exact row (max, 1/sum) without writing logits ------
__global__ void __launch_bounds__(256, 2)
stats_kernel(const __half* __restrict__ Qhi, const __half* __restrict__ Qlo,
             const __half* __restrict__ Kp,
             float* __restrict__ rm, float* __restrict__ ri)
{
    constexpr int LDQ = 72, LDK = 72, LDC = 72;
    constexpr int OFF_Q = 0;       // Qh 18432 + Ql 18432
    constexpr int OFF_K = 36864;   // 2 x 9216
    constexpr int OFF_C = 55296;   // 36864
    constexpr int OFF_M = 92160;   // 512
    constexpr int OFF_S = 92672;   // 512 ; total 93184

    extern __shared__ char smem[];
    const uint32_t sbase = smem_to_u32(smem);
    const int tid = threadIdx.x, wid = tid >> 5;
    const int z = blockIdx.z, m0 = blockIdx.y * 128;
    const int wm0 = (wid & 3) * 32, wn0 = (wid >> 2) * 32;

    const __half* Qh_g = Qhi + ((size_t)z * S + m0) * DK;
    const __half* Ql_g = Qlo + ((size_t)z * S + m0) * DK;
    const __half* K_g  = Kp  + (size_t)z * S * DK;

    for (int u = tid; u < 128 * 8; u += 256) {
        int r = u >> 3, g = u & 7;
        cp_async16(sbase + OFF_Q + (uint32_t)(r * LDQ + g * 8) * 2, Qh_g + (size_t)r * DK + g * 8);
        cp_async16(sbase + OFF_Q + 18432 + (uint32_t)(r * LDQ + g * 8) * 2, Ql_g + (size_t)r * DK + g * 8);
    }
    CP_COMMIT();
    auto stage_k = [&](int s, int ch) {
        int k0 = ch << 6;
        for (int u = tid; u < 64 * 8; u += 256) {
            int r = u >> 3, g = u & 7;
            cp_async16(sbase + OFF_K + s * 9216 + (uint32_t)(r * LDK + g * 8) * 2,
                       K_g + (size_t)(k0 + r) * DK + g * 8);
        }
        CP_COMMIT();
    };
    stage_k(0, 0);

    float* sM = reinterpret_cast<float*>(smem + OFF_M);
    float* sS = reinterpret_cast<float*>(smem + OFF_S);
    if (tid < 128) { sM[tid] = -CUDART_INF_F; sS[tid] = 0.0f; }

    const __half* sQh = reinterpret_cast<const __half*>(smem + OFF_Q);
    const __half* sQl = reinterpret_cast<const __half*>(smem + OFF_Q + 18432);
    float* Cs = reinterpret_cast<float*>(smem + OFF_C);

    for (int ch = 0; ch < 32; ch++) {
        if (ch + 1 < 32) { stage_k((ch + 1) & 1, ch + 1); CP_WAIT(1); }
        else             { CP_WAIT(0); }
        __syncthreads();
        const __half* sK = reinterpret_cast<const __half*>(smem + OFF_K + (ch & 1) * 9216);

        wmma::fragment<wmma::accumulator, 16, 16, 16, float> acc[2][2];
        #pragma unroll
        for (int mi = 0; mi < 2; mi++)
            #pragma unroll
            for (int ni = 0; ni < 2; ni++) wmma::fill_fragment(acc[mi][ni], 0.0f);

        #pragma unroll
        for (int ks = 0; ks < 4; ks++) {
            wmma::fragment<wmma::matrix_a, 16, 16, 16, __half, wmma::row_major> ah[2], al[2];
            wmma::fragment<wmma::matrix_b, 16, 16, 16, __half, wmma::col_major> bf[2];
            #pragma unroll
            for (int mi = 0; mi < 2; mi++) {
                wmma::load_matrix_sync(ah[mi], sQh + (wm0 + mi * 16) * LDQ + ks * 16, LDQ);
                wmma::load_matrix_sync(al[mi], sQl + (wm0 + mi * 16) * LDQ + ks * 16, LDQ);
            }
            #pragma unroll
            for (int ni = 0; ni < 2; ni++)
                wmma::load_matrix_sync(bf[ni], sK + (wn0 + ni * 16) * LDK + ks * 16, LDK);
            #pragma unroll
            for (int mi = 0; mi < 2; mi++)
                #pragma unroll
                for (int ni = 0; ni < 2; ni++) {
                    wmma::mma_sync(acc[mi][ni], ah[mi], bf[ni], acc[mi][ni]);
                    wmma::mma_sync(acc[mi][ni], al[mi], bf[ni], acc[mi][ni]);
                }
        }
        #pragma unroll
        for (int mi = 0; mi < 2; mi++)
            #pragma unroll
            for (int ni = 0; ni < 2; ni++)
                wmma::store_matrix_sync(Cs + (wm0 + mi * 16) * LDC + wn0 + ni * 16,
                                        acc[mi][ni], LDC, wmma::mem_row_major);
        __syncthreads();

        #pragma unroll
        for (int it = 0; it < 8; it++) {
            int idx = it * 256 + tid;
            int r = idx >> 4, c4 = (idx & 15) * 4;
            float4 v = *reinterpret_cast<const float4*>(Cs + r * LDC + c4);
            v.x *= 0.125f; v.y *= 0.125f; v.z *= 0.125f; v.w *= 0.125f;
            float tm = fmaxf(fmaxf(v.x, v.y), fmaxf(v.z, v.w));
            #pragma unroll
            for (int o = 8; o > 0; o >>= 1) tm = fmaxf(tm, __shfl_xor_sync(0xFFFFFFFFu, tm, o));
            float ts = __expf(v.x - tm) + __expf(v.y - tm) + __expf(v.z - tm) + __expf(v.w - tm);
            #pragma unroll
            for (int o = 8; o > 0; o >>= 1) ts += __shfl_xor_sync(0xFFFFFFFFu, ts, o);
            if ((tid & 15) == 0) {
                float om = sM[r], os = sS[r];
                float nm = fmaxf(om, tm);
                sS[r] = os * __expf(om - nm) + ts * __expf(tm - nm);
                sM[r] = nm;
            }
        }
        __syncthreads();
    }

    if (tid < 128) {
        size_t ro = (size_t)z * S + m0 + tid;
        rm[ro] = sM[tid];
        ri[ro] = 1.0f / sS[tid];
    }
}

// ---------------- PV2: recompute QK^T, softmax -> probs (only attn write), PV ------
// Probs used single-fp16 in PV (error only affects 'values', not attention output).
__global__ void __launch_bounds__(256, 2)
pv2_kernel(float* __restrict__ attn,
           const float* __restrict__ rm, const float* __restrict__ ri,
           const __half* __restrict__ Qhi, const __half* __restrict__ Qlo,
           const __half* __restrict__ Kp, const __half* __restrict__ Vt)
{
    constexpr int LDQ = 72, LDK = 72, LDV = 72, LDCF = 72, LDP = 72;
    constexpr int OFF_Q  = 0;       // 36864
    constexpr int OFF_K  = 36864;   // 2 x 9216
    constexpr int OFF_V  = 55296;   // 2 x 9216
    constexpr int OFF_C  = 73728;   // 36864 (fp32 logits / fp16 probs overlay)
    constexpr int OFF_RM = 110592;  // 512
    constexpr int OFF_RI = 111104;  // 512 ; total 111616

    extern __shared__ char smem[];
    const uint32_t sbase = smem_to_u32(smem);
    const int tid = threadIdx.x, wid = tid >> 5;
    const int z = blockIdx.z, m0 = blockIdx.y * 128;
    const int wm0 = (wid & 3) * 32, wn0 = (wid >> 2) * 32;

    const __half* Qh_g = Qhi + ((size_t)z * S + m0) * DK;
    const __half* Ql_g = Qlo + ((size_t)z * S + m0) * DK;
    const __half* K_g  = Kp  + (size_t)z * S * DK;
    const __half* V_g  = Vt  + (size_t)z * DK * S;
    float* attnZ = attn + (size_t)z * S * S;

    for (int u = tid; u < 128 * 8; u += 256) {
        int r = u >> 3, g = u & 7;
        cp_async16(sbase + OFF_Q + (uint32_t)(r * LDQ + g * 8) * 2, Qh_g + (size_t)r * DK + g * 8);
        cp_async16(sbase + OFF_Q + 18432 + (uint32_t)(r * LDQ + g * 8) * 2, Ql_g + (size_t)r * DK + g * 8);
    }
    CP_COMMIT();
    auto stage_kv = [&](int s, int ch) {
        int k0 = ch << 6;
        for (int u = tid; u < 64 * 8; u += 256) {
            int r = u >> 3, g = u & 7;
            cp_async16(sbase + OFF_K + s * 9216 + (uint32_t)(r * LDK + g * 8) * 2,
                       K_g + (size_t)(k0 + r) * DK + g * 8);
            cp_async16(sbase + OFF_V + s * 9216 + (uint32_t)(r * LDV + g * 8) * 2,
                       V_g + (size_t)r * S + k0 + g * 8);
        }
        CP_COMMIT();
    };
    stage_kv(0, 0);

    float* sRm = reinterpret_cast<float*>(smem + OFF_RM);
    float* sRi = reinterpret_cast<float*>(smem + OFF_RI);
    if (tid < 128) {
        size_t ro = (size_t)z * S + m0 + tid;
        sRm[tid] = rm[ro];
        sRi[tid] = ri[ro];
    }

    const __half* sQh = reinterpret_cast<const __half*>(smem + OFF_Q);
    const __half* sQl = reinterpret_cast<const __half*>(smem + OFF_Q + 18432);
    float* Csf = reinterpret_cast<float*>(smem + OFF_C);
    __half* Ph = reinterpret_cast<__half*>(smem + OFF_C);

    wmma::fragment<wmma::accumulator, 16, 16, 16, float> pacc[2][2];
    #pragma unroll
    for (int mi = 0; mi < 2; mi++)
        #pragma unroll
        for (int ni = 0; ni < 2; ni++) wmma::fill_fragment(pacc[mi][ni], 0.0f);

    for (int ch = 0; ch < 32; ch++) {
        __syncthreads();   // prev PV MMA complete: KV buf (ch+1)&1 and Ph reusable

        if (ch + 1 < 32) { stage_kv((ch + 1) & 1, ch + 1); CP_WAIT(1); }
        else             { CP_WAIT(0); }
        __syncthreads();   // KV[ch] visible to all threads

        const __half* sK = reinterpret_cast<const __half*>(smem + OFF_K + (ch & 1) * 9216);
        const __half* sV = reinterpret_cast<const __half*>(smem + OFF_V + (ch & 1) * 9216);

        // ---- QK^T recompute (identical arithmetic to stats_kernel) ----
        wmma::fragment<wmma::accumulator, 16, 16, 16, float> qacc[2][2];
        #pragma unroll
        for (int mi = 0; mi < 2; mi++)
            #pragma unroll
            for (int ni = 0; ni < 2; ni++) wmma::fill_fragment(qacc[mi][ni], 0.0f);
        #pragma unroll
        for (int ks = 0; ks < 4; ks++) {
            wmma::fragment<wmma::matrix_a, 16, 16, 16, __half, wmma::row_major> ah[2], al[2];
            wmma::fragment<wmma::matrix_b, 16, 16, 16, __half, wmma::col_major> bf[2];
            #pragma unroll
            for (int mi = 0; mi < 2; mi++) {
                wmma::load_matrix_sync(ah[mi], sQh + (wm0 + mi * 16) * LDQ + ks * 16, LDQ);
                wmma::load_matrix_sync(al[mi], sQl + (wm0 + mi * 16) * LDQ + ks * 16, LDQ);
            }
            #pragma unroll
            for (int ni = 0; ni < 2; ni++)
                wmma::load_matrix_sync(bf[ni], sK + (wn0 + ni * 16) * LDK + ks * 16, LDK);
            #pragma unroll
            for (int mi = 0; mi < 2; mi++)
                #pragma unroll
                for (int ni = 0; ni < 2; ni++) {
                    wmma::mma_sync(qacc[mi][ni], ah[mi], bf[ni], qacc[mi][ni]);
                    wmma::mma_sync(qacc[mi][ni], al[mi], bf[ni], qacc[mi][ni]);
                }
        }
        #pragma unroll
        for (int mi = 0; mi < 2; mi++)
            #pragma unroll
            for (int ni = 0; ni < 2; ni++)
                wmma::store_matrix_sync(Csf + (wm0 + mi * 16) * LDCF + wn0 + ni * 16,
                                        qacc[mi][ni], LDCF, wmma::mem_row_major);
        __syncthreads();

        // ---- transform: exp-normalize, write probs to attn, in-place fp16 pack ----
        const int n0 = ch << 6;
        #pragma unroll
        for (int it = 0; it < 8; it++) {
            int idx = it * 256 + tid;
            int r = idx >> 4, c4 = (idx & 15) * 4;
            float4 v = *reinterpret_cast<const float4*>(Csf + r * LDCF + c4);
            float m = sRm[r], rv = sRi[r];
            float4 p;
            p.x = __expf(v.x * 0.125f - m) * rv;
            p.y = __expf(v.y * 0.125f - m) * rv;
            p.z = __expf(v.z * 0.125f - m) * rv;
            p.w = __expf(v.w * 0.125f - m) * rv;
            *reinterpret_cast<float4*>(attnZ + (size_t)(m0 + r) * S + n0 + c4) = p;
            __syncwarp();   // all Csf reads of this warp's rows complete before overlay
            *reinterpret_cast<uint2*>(Ph + r * LDP + c4) =
                make_uint2(pack2h(p.x, p.y), pack2h(p.z, p.w));
        }
        __syncthreads();

        // ---- PV MMA, single pass on fp16 probs ----
        #pragma unroll
        for (int ks = 0; ks < 4; ks++) {
            wmma::fragment<wmma::matrix_a, 16, 16, 16, __half, wmma::row_major> af[2];
            wmma::fragment<wmma::matrix_b, 16, 16, 16, __half, wmma::col_major> bf[2];
            #pragma unroll
            for (int mi = 0; mi < 2; mi++)
                wmma::load_matrix_sync(af[mi], Ph + (wm0 + mi * 16) * LDP + ks * 16, LDP);
            #pragma unroll
            for (int ni = 0; ni < 2; ni++)
                wmma::load_matrix_sync(bf[ni], sV + (wn0 + ni * 16) * LDV + ks * 16, LDV);
            #pragma unroll
            for (int mi = 0; mi < 2; mi++)
                #pragma unroll
                for (int ni = 0; ni < 2; ni++)
                    wmma::mma_sync(pacc[mi][ni], af[mi], bf[ni], pacc[mi][ni]);
        }
    }
    __syncthreads();

    // ---- epilogue: values -> g_vals single fp16 [B,S,E] ----
    #pragma unroll
    for (int mi = 0; mi < 2; mi++)
        #pragma unroll
        for (int ni = 0; ni < 2; ni++)
            wmma::store_matrix_sync(Csf + (wm0 + mi * 16) * 72 + wn0 + ni * 16,
                                    pacc[mi][ni], 72, wmma::mem_row_major);
    __syncthreads();

    int b = z >> 4, h = z & 15;
    #pragma unroll
    for (int it = 0; it < 8; it++) {
        int idx = it * 256 + tid;
        int r = idx >> 4;
        int c4 = (idx & 15) * 4;
        float4 v = *reinterpret_cast<const float4*>(Csf + r * 72 + c4);
        size_t off = (size_t)(b * S + m0 + r) * E + h * DK + c4;
        *reinterpret_cast<uint2*>(g_vals + off) =
            make_uint2(pack2h(v.x, v.y), pack2h(v.z, v.w));
    }
}

// ---------------- pre-kernels ----------------
__global__ void __launch_bounds__(256)
split_kernel(const float* __restrict__ src, __half* __restrict__ dh,
             __half* __restrict__ dl, size_t n)
{
    size_t i = ((size_t)blockIdx.x * 256 + threadIdx.x) * 4;
    if (i >= n) return;
    float4 v = *reinterpret_cast<const float4*>(src + i);
    uint32_t h0, l0, h1, l1;
    pack_split2h(v.x, v.y, h0, l0);
    pack_split2h(v.z, v.w, h1, l1);
    *reinterpret_cast<uint2*>(dh + i) = make_uint2(h0, h1);
    *reinterpret_cast<uint2*>(dl + i) = make_uint2(l0, l1);
}

__global__ void __launch_bounds__(256)
transpose_h(const float* __restrict__ W, __half* __restrict__ Th, int R, int C)
{
    __shared__ float t[32][33];
    int c0 = blockIdx.x * 32, r0 = blockIdx.y * 32;
    int tx = threadIdx.x & 31, ty = threadIdx.x >> 5;
    for (int j = ty; j < 32; j += 8)
        t[j][tx] = W[(size_t)(r0 + j) * C + c0 + tx];
    __syncthreads();
    for (int j = ty; j < 32; j += 8)
        Th[(size_t)(c0 + j) * R + r0 + tx] = __float2half(t[tx][j]);
}

// ---------------- launch ----------------
extern "C" void kernel_launch(void* const* d_in, const int* /*in_sizes*/, int /*n_in*/,
                              void* d_out, int /*out_size*/)
{
    const float* x    = (const float*)d_in[0];
    const float* Wqkv = (const float*)d_in[1];
    const float* bqkv = (const float*)d_in[2];
    const float* Wout = (const float*)d_in[3];
    const float* bout = (const float*)d_in[4];

    float* out  = (float*)d_out;
    float* attn = out + (size_t)M_TOK * E;

    __half *xhi, *xlo, *Wq, *Wo, *Qhi, *Qlo, *Kp, *Vt, *Vl;
    float *rm, *ri;
    cudaGetSymbolAddress((void**)&xhi, g_xhi);
    cudaGetSymbolAddress((void**)&xlo, g_xlo);
    cudaGetSymbolAddress((void**)&Wq,  g_Wqt);
    cudaGetSymbolAddress((void**)&Wo,  g_Wot);
    cudaGetSymbolAddress((void**)&Qhi, g_Qhi);
    cudaGetSymbolAddress((void**)&Qlo, g_Qlo);
    cudaGetSymbolAddress((void**)&Kp,  g_K);
    cudaGetSymbolAddress((void**)&Vt,  g_Vt);
    cudaGetSymbolAddress((void**)&Vl,  g_vals);
    cudaGetSymbolAddress((void**)&rm,  g_rm);
    cudaGetSymbolAddress((void**)&ri,  g_ri);

    constexpr int SM_BIG   = 69632;
    constexpr int SM_STATS = 93184;
    constexpr int SM_PV2   = 111616;
    cudaFuncSetAttribute(gemm_async<128, 128, 2, EpiQKV>,
                         cudaFuncAttributeMaxDynamicSharedMemorySize, SM_BIG);
    cudaFuncSetAttribute(gemm_async<128, 128, 1, EpiOut>,
                         cudaFuncAttributeMaxDynamicSharedMemorySize, SM_BIG);
    cudaFuncSetAttribute(stats_kernel,
                         cudaFuncAttributeMaxDynamicSharedMemorySize, SM_STATS);
    cudaFuncSetAttribute(pv2_kernel,
                         cudaFuncAttributeMaxDynamicSharedMemorySize, SM_PV2);

    // 0) operand prep
    transpose_h<<<dim3(3 * E / 32, E / 32), 256>>>(Wqkv, Wq, E, 3 * E);
    transpose_h<<<dim3(E / 32, E / 32), 256>>>(Wout, Wo, E, E);
    split_kernel<<<(unsigned)((size_t)M_TOK * E / 4 / 256), 256>>>(x, xhi, xlo, (size_t)M_TOK * E);

    // 1) QKV projection (A = x split, 2-pass)
    gemm_async<128, 128, 2, EpiQKV><<<dim3(3 * E / 128, M_TOK / 128, 1), 256, SM_BIG>>>(
        xhi, xlo, Wq, E, 0, 0, EpiQKV{bqkv});

    // 2) stats: exact per-row (max, 1/sum)
    stats_kernel<<<dim3(1, S / 128, BH), 256, SM_STATS>>>(Qhi, Qlo, Kp, rm, ri);

    // 3) PV2: recompute logits, probs -> attn (single pass), PV (probs single fp16)
    pv2_kernel<<<dim3(1, S / 128, BH), 256, SM_PV2>>>(attn, rm, ri, Qhi, Qlo, Kp, Vt);

    // 4) output projection (A = vals single fp16, 1-pass)
    gemm_async<128, 128, 1, EpiOut><<<dim3(E / 128, M_TOK / 128, 1), 256, SM_BIG>>>(
        Vl, nullptr, Wo, E, 0, 0, EpiOut{bout, out});
}